// round 3
// baseline (speedup 1.0000x reference)
#include <cuda_runtime.h>
#include <math.h>

#define BATCH 2
#define CTX   2048
#define DM    1024
#define NH    16
#define HD    64
#define BT    (BATCH*CTX)   // 4096

// ---------------- scratch (device globals; no allocation allowed) ----------
__device__ float g_Q[BT * DM];
__device__ float g_K[BT * DM];
__device__ float g_V[BT * DM];
__device__ float g_C[BT * DM];
__device__ float g_Xr[BT * DM];
__device__ float g_Wr[4 * DM * DM];

// ---------------- helpers ---------------------------------------------------
__device__ __forceinline__ float rna(float x) {
    unsigned u;
    asm("cvt.rna.tf32.f32 %0, %1;" : "=r"(u) : "f"(x));
    return __uint_as_float(u);
}

__device__ __forceinline__ void mma_tf32(float* d, const unsigned* a, unsigned b0, unsigned b1) {
    asm volatile(
        "mma.sync.aligned.m16n8k8.row.col.f32.tf32.tf32.f32 "
        "{%0,%1,%2,%3}, {%4,%5,%6,%7}, {%8,%9}, {%0,%1,%2,%3};"
        : "+f"(d[0]), "+f"(d[1]), "+f"(d[2]), "+f"(d[3])
        : "r"(a[0]), "r"(a[1]), "r"(a[2]), "r"(a[3]),
          "r"(b0), "r"(b1));
}

__device__ __forceinline__ void cp16(float* s, const float* g) {
    unsigned sa = (unsigned)__cvta_generic_to_shared(s);
    asm volatile("cp.async.ca.shared.global [%0], [%1], 16;" :: "r"(sa), "l"(g));
}

// ---------------- pre-round inputs to tf32 ----------------------------------
__global__ __launch_bounds__(256) void round_k(const float4* __restrict__ in,
                                               float4* __restrict__ out, int n4) {
    int i = blockIdx.x * 256 + threadIdx.x;
    if (i < n4) {
        float4 v = in[i];
        v.x = rna(v.x); v.y = rna(v.y); v.z = rna(v.z); v.w = rna(v.w);
        out[i] = v;
    }
}

// ============================================================================
// tf32 GEMM: C[M=4096, N=1024] = A @ B (+bias). BM=BN=128, BK=32.
// 256 threads = 8 warps (4 m x 2 n), warp tile 32x64, mma m16n8k8.
// ============================================================================
#define AS_LD 36
#define BS_LD 136
#define AS_SZ (128 * AS_LD)
#define BS_SZ (32 * BS_LD)
#define GEMM_SMEM ((2 * AS_SZ + 2 * BS_SZ) * (int)sizeof(float))

__global__ __launch_bounds__(256) void gemm_tf32(
    const float* __restrict__ A, const float* __restrict__ B,
    const float* __restrict__ bias, float* __restrict__ C)
{
    extern __shared__ float smg[];
    float* As = smg;
    float* Bs = smg + 2 * AS_SZ;

    const int tid = threadIdx.x;
    const int lane = tid & 31, wid = tid >> 5;
    const int g = lane >> 2, t = lane & 3;
    const int wm = wid & 3, wn = wid >> 2;
    const int row0 = blockIdx.y * 128, col0 = blockIdx.x * 128;

    float acc[2][8][4];
    #pragma unroll
    for (int mt = 0; mt < 2; mt++)
        #pragma unroll
        for (int nt = 0; nt < 8; nt++)
            #pragma unroll
            for (int r = 0; r < 4; r++) acc[mt][nt][r] = 0.f;

    auto issue = [&](int k0, int buf) {
        float* ab = As + buf * AS_SZ;
        float* bb = Bs + buf * BS_SZ;
        #pragma unroll
        for (int i = 0; i < 4; i++) {
            int idx = tid + i * 256;
            int r = idx >> 3, c = idx & 7;
            cp16(ab + r * AS_LD + 4 * c, A + (size_t)(row0 + r) * DM + k0 + 4 * c);
        }
        #pragma unroll
        for (int i = 0; i < 4; i++) {
            int idx = tid + i * 256;
            int r = idx >> 5, c = idx & 31;
            cp16(bb + r * BS_LD + 4 * c, B + (size_t)(k0 + r) * DM + col0 + 4 * c);
        }
        asm volatile("cp.async.commit_group;");
    };

    issue(0, 0);
    const int NT = DM / 32;   // 32 k-tiles
    for (int it = 0; it < NT; ++it) {
        if (it + 1 < NT) {
            issue((it + 1) * 32, (it + 1) & 1);
            asm volatile("cp.async.wait_group 1;");
        } else {
            asm volatile("cp.async.wait_group 0;");
        }
        __syncthreads();

        const float* ab = As + (it & 1) * AS_SZ;
        const float* bb = Bs + (it & 1) * BS_SZ;
        #pragma unroll
        for (int ks = 0; ks < 4; ks++) {
            unsigned a[2][4];
            #pragma unroll
            for (int mt = 0; mt < 2; mt++) {
                const float* ap = ab + (wm * 32 + mt * 16 + g) * AS_LD + ks * 8 + t;
                a[mt][0] = __float_as_uint(ap[0]);
                a[mt][1] = __float_as_uint(ap[8 * AS_LD]);
                a[mt][2] = __float_as_uint(ap[4]);
                a[mt][3] = __float_as_uint(ap[8 * AS_LD + 4]);
            }
            #pragma unroll
            for (int nt = 0; nt < 8; nt++) {
                const float* bp = bb + (ks * 8 + t) * BS_LD + wn * 64 + nt * 8 + g;
                unsigned b0 = __float_as_uint(bp[0]);
                unsigned b1 = __float_as_uint(bp[4 * BS_LD]);
                mma_tf32(acc[0][nt], a[0], b0, b1);
                mma_tf32(acc[1][nt], a[1], b0, b1);
            }
        }
        __syncthreads();
    }

    #pragma unroll
    for (int mt = 0; mt < 2; mt++) {
        int r = row0 + wm * 32 + mt * 16 + g;
        #pragma unroll
        for (int nt = 0; nt < 8; nt++) {
            int c = col0 + wn * 64 + nt * 8 + 2 * t;
            float2 v0 = make_float2(acc[mt][nt][0], acc[mt][nt][1]);
            float2 v1 = make_float2(acc[mt][nt][2], acc[mt][nt][3]);
            if (bias) {
                float bx = bias[c], by = bias[c + 1];
                v0.x += bx; v0.y += by;
                v1.x += bx; v1.y += by;
            }
            *(float2*)&C[(size_t)r * DM + c]       = v0;
            *(float2*)&C[(size_t)(r + 8) * DM + c] = v1;
        }
    }
}

// ============================================================================
// Flash attention (causal, tf32 mma). 128 q-rows/CTA, KT=64 per iter.
// 8 warps, warp owns 16 q-rows. Output is pre-rounded to tf32 for out-proj.
// ============================================================================
#define FS_LD 68
#define FLASH_SMEM ((128 * FS_LD + 64 * FS_LD + 64 * FS_LD + 128 * FS_LD) * (int)sizeof(float))

__global__ __launch_bounds__(256) void flash_tf32(
    const float* __restrict__ Q, const float* __restrict__ K,
    const float* __restrict__ V, float* __restrict__ O)
{
    extern __shared__ float smf[];
    float* Qs = smf;                    // [128][68]  (q, d)
    float* Ks = Qs + 128 * FS_LD;       // [64][68]   (key, d)
    float* Vs = Ks + 64 * FS_LD;        // [64][68]   (d, key)  transposed
    float* Ps = Vs + 64 * FS_LD;        // [128][68]  (q, key)

    const int tid = threadIdx.x;
    const int lane = tid & 31, wid = tid >> 5;
    const int g = lane >> 2, t = lane & 3;
    const int q0 = blockIdx.x * 128;
    const int h = blockIdx.y, b = blockIdx.z;
    const size_t base = ((size_t)b * CTX) * DM + h * HD;
    const float scale = 0.125f;

    // load Q tile (scaled + rounded)
    #pragma unroll
    for (int i = 0; i < 8; i++) {
        int idx = tid + i * 256;
        int q = idx >> 4, c4 = idx & 15;
        float4 v = *(const float4*)(Q + base + (size_t)(q0 + q) * DM + 4 * c4);
        v.x = rna(v.x * scale); v.y = rna(v.y * scale);
        v.z = rna(v.z * scale); v.w = rna(v.w * scale);
        *(float4*)(Qs + q * FS_LD + 4 * c4) = v;
    }

    float m0 = -INFINITY, m1 = -INFINITY, l0 = 0.f, l1 = 0.f;
    float o[8][4];
    #pragma unroll
    for (int dt = 0; dt < 8; dt++)
        #pragma unroll
        for (int r = 0; r < 4; r++) o[dt][r] = 0.f;

    const int nkv = q0 / 64 + 2;
    for (int tkv = 0; tkv < nkv; ++tkv) {
        const int kb = tkv * 64;

        // load K (row-major, rounded) and V (transposed d-major, rounded)
        #pragma unroll
        for (int i = 0; i < 4; i++) {
            int idx = tid + i * 256;
            int kk = idx >> 4, c4 = idx & 15;
            float4 v = *(const float4*)(K + base + (size_t)(kb + kk) * DM + 4 * c4);
            v.x = rna(v.x); v.y = rna(v.y); v.z = rna(v.z); v.w = rna(v.w);
            *(float4*)(Ks + kk * FS_LD + 4 * c4) = v;
            float4 w = *(const float4*)(V + base + (size_t)(kb + kk) * DM + 4 * c4);
            Vs[(4 * c4 + 0) * FS_LD + kk] = rna(w.x);
            Vs[(4 * c4 + 1) * FS_LD + kk] = rna(w.y);
            Vs[(4 * c4 + 2) * FS_LD + kk] = rna(w.z);
            Vs[(4 * c4 + 3) * FS_LD + kk] = rna(w.w);
        }
        __syncthreads();

        // S = Q @ K^T   (warp: 16 x 64)
        float s[8][4];
        #pragma unroll
        for (int nt = 0; nt < 8; nt++)
            #pragma unroll
            for (int r = 0; r < 4; r++) s[nt][r] = 0.f;

        #pragma unroll
        for (int ks = 0; ks < 8; ks++) {
            unsigned a[4];
            const float* qp = Qs + (wid * 16 + g) * FS_LD + ks * 8 + t;
            a[0] = __float_as_uint(qp[0]);
            a[1] = __float_as_uint(qp[8 * FS_LD]);
            a[2] = __float_as_uint(qp[4]);
            a[3] = __float_as_uint(qp[8 * FS_LD + 4]);
            #pragma unroll
            for (int nt = 0; nt < 8; nt++) {
                const float* kp = Ks + (nt * 8 + g) * FS_LD + ks * 8 + t;
                mma_tf32(s[nt], a, __float_as_uint(kp[0]), __float_as_uint(kp[4]));
            }
        }

        const int r0 = q0 + wid * 16 + g;
        const int r1 = r0 + 8;

        // causal mask (only diagonal-crossing tiles)
        if (kb + 63 > q0) {
            #pragma unroll
            for (int nt = 0; nt < 8; nt++) {
                #pragma unroll
                for (int j = 0; j < 2; j++) {
                    int key = kb + nt * 8 + 2 * t + j;
                    if (key > r0) s[nt][j]     = -1e30f;
                    if (key > r1) s[nt][2 + j] = -1e30f;
                }
            }
        }

        // online softmax
        float rm0 = -1e30f, rm1 = -1e30f;
        #pragma unroll
        for (int nt = 0; nt < 8; nt++) {
            rm0 = fmaxf(rm0, fmaxf(s[nt][0], s[nt][1]));
            rm1 = fmaxf(rm1, fmaxf(s[nt][2], s[nt][3]));
        }
        rm0 = fmaxf(rm0, __shfl_xor_sync(0xffffffffu, rm0, 1));
        rm0 = fmaxf(rm0, __shfl_xor_sync(0xffffffffu, rm0, 2));
        rm1 = fmaxf(rm1, __shfl_xor_sync(0xffffffffu, rm1, 1));
        rm1 = fmaxf(rm1, __shfl_xor_sync(0xffffffffu, rm1, 2));

        float mn0 = fmaxf(m0, rm0), mn1 = fmaxf(m1, rm1);
        float c0 = __expf(m0 - mn0), c1 = __expf(m1 - mn1);
        float rs0 = 0.f, rs1 = 0.f;
        #pragma unroll
        for (int nt = 0; nt < 8; nt++) {
            s[nt][0] = __expf(s[nt][0] - mn0);
            s[nt][1] = __expf(s[nt][1] - mn0);
            s[nt][2] = __expf(s[nt][2] - mn1);
            s[nt][3] = __expf(s[nt][3] - mn1);
            rs0 += s[nt][0] + s[nt][1];
            rs1 += s[nt][2] + s[nt][3];
        }
        rs0 += __shfl_xor_sync(0xffffffffu, rs0, 1);
        rs0 += __shfl_xor_sync(0xffffffffu, rs0, 2);
        rs1 += __shfl_xor_sync(0xffffffffu, rs1, 1);
        rs1 += __shfl_xor_sync(0xffffffffu, rs1, 2);

        l0 = l0 * c0 + rs0; m0 = mn0;
        l1 = l1 * c1 + rs1; m1 = mn1;
        #pragma unroll
        for (int dt = 0; dt < 8; dt++) {
            o[dt][0] *= c0; o[dt][1] *= c0;
            o[dt][2] *= c1; o[dt][3] *= c1;
        }

        // write P (rounded) to smem
        #pragma unroll
        for (int nt = 0; nt < 8; nt++) {
            float2 p0 = make_float2(rna(s[nt][0]), rna(s[nt][1]));
            float2 p1 = make_float2(rna(s[nt][2]), rna(s[nt][3]));
            *(float2*)(Ps + (wid * 16 + g) * FS_LD + nt * 8 + 2 * t)     = p0;
            *(float2*)(Ps + (wid * 16 + g + 8) * FS_LD + nt * 8 + 2 * t) = p1;
        }
        __syncwarp();

        // O += P @ V
        #pragma unroll
        for (int ks = 0; ks < 8; ks++) {
            unsigned a[4];
            const float* pp = Ps + (wid * 16 + g) * FS_LD + ks * 8 + t;
            a[0] = __float_as_uint(pp[0]);
            a[1] = __float_as_uint(pp[8 * FS_LD]);
            a[2] = __float_as_uint(pp[4]);
            a[3] = __float_as_uint(pp[8 * FS_LD + 4]);
            #pragma unroll
            for (int dt = 0; dt < 8; dt++) {
                const float* vp = Vs + (dt * 8 + g) * FS_LD + ks * 8 + t;
                mma_tf32(o[dt], a, __float_as_uint(vp[0]), __float_as_uint(vp[4]));
            }
        }
        __syncthreads();
    }

    // epilogue: normalize, round to tf32 (feeds out-proj GEMM), store ctx
    float i0 = 1.f / l0, i1 = 1.f / l1;
    const int r0 = q0 + wid * 16 + g;
    #pragma unroll
    for (int dt = 0; dt < 8; dt++) {
        int c = dt * 8 + 2 * t;
        float2 v0 = make_float2(rna(o[dt][0] * i0), rna(o[dt][1] * i0));
        float2 v1 = make_float2(rna(o[dt][2] * i1), rna(o[dt][3] * i1));
        *(float2*)(O + base + (size_t)r0 * DM + c)       = v0;
        *(float2*)(O + base + (size_t)(r0 + 8) * DM + c) = v1;
    }
}

// ============================================================================
// launch
// ============================================================================
extern "C" void kernel_launch(void* const* d_in, const int* in_sizes, int n_in,
                              void* d_out, int out_size)
{
    const float* x  = (const float*)d_in[0];
    const float* Wq = (const float*)d_in[1];
    const float* Wk = (const float*)d_in[2];
    const float* Wv = (const float*)d_in[3];
    const float* Wo = (const float*)d_in[4];
    const float* bo = (const float*)d_in[5];
    float* out = (float*)d_out;

    float *Qp, *Kp, *Vp, *Cp, *Xr, *Wr;
    cudaGetSymbolAddress((void**)&Qp, g_Q);
    cudaGetSymbolAddress((void**)&Kp, g_K);
    cudaGetSymbolAddress((void**)&Vp, g_V);
    cudaGetSymbolAddress((void**)&Cp, g_C);
    cudaGetSymbolAddress((void**)&Xr, g_Xr);
    cudaGetSymbolAddress((void**)&Wr, g_Wr);

    cudaFuncSetAttribute(gemm_tf32, cudaFuncAttributeMaxDynamicSharedMemorySize, GEMM_SMEM);
    cudaFuncSetAttribute(flash_tf32, cudaFuncAttributeMaxDynamicSharedMemorySize, FLASH_SMEM);

    // pre-round x and weights to tf32 (rna)
    const int NX4 = BT * DM / 4;   // 1048576
    const int NW4 = DM * DM / 4;   // 262144
    round_k<<<NX4 / 256, 256>>>((const float4*)x,  (float4*)Xr, NX4);
    round_k<<<NW4 / 256, 256>>>((const float4*)Wq, (float4*)(Wr + 0 * DM * DM), NW4);
    round_k<<<NW4 / 256, 256>>>((const float4*)Wk, (float4*)(Wr + 1 * DM * DM), NW4);
    round_k<<<NW4 / 256, 256>>>((const float4*)Wv, (float4*)(Wr + 2 * DM * DM), NW4);
    round_k<<<NW4 / 256, 256>>>((const float4*)Wo, (float4*)(Wr + 3 * DM * DM), NW4);

    dim3 ggrid(DM / 128, BT / 128);   // (8, 32)
    gemm_tf32<<<ggrid, 256, GEMM_SMEM>>>(Xr, Wr + 0 * DM * DM, nullptr, Qp);
    gemm_tf32<<<ggrid, 256, GEMM_SMEM>>>(Xr, Wr + 1 * DM * DM, nullptr, Kp);
    gemm_tf32<<<ggrid, 256, GEMM_SMEM>>>(Xr, Wr + 2 * DM * DM, nullptr, Vp);

    dim3 fgrid(CTX / 128, NH, BATCH);  // (16, 16, 2)
    flash_tf32<<<fgrid, 256, FLASH_SMEM>>>(Qp, Kp, Vp, Cp);

    gemm_tf32<<<ggrid, 256, GEMM_SMEM>>>(Cp, Wr + 3 * DM * DM, bo, out);
}

// round 5
// speedup vs baseline: 1.7186x; 1.7186x over previous
#include <cuda_runtime.h>
#include <cuda_fp16.h>
#include <math.h>
#include <stdint.h>

#define BATCH 2
#define CTX   2048
#define DM    1024
#define NH    16
#define HD    64
#define BT    (BATCH*CTX)   // 4096

// ---------------- scratch (device globals; no allocation allowed) ----------
__device__ __half g_Xh[BT * DM];
__device__ __half g_Wh[4 * DM * DM];   // transposed weights [N][K], fp16
__device__ __half g_Qh[BT * DM];
__device__ __half g_Kh[BT * DM];
__device__ __half g_Vh[BT * DM];
__device__ __half g_Ch[BT * DM];

// ---------------- helpers ---------------------------------------------------
__device__ __forceinline__ void mma_f16(float* d, const uint32_t* a, uint32_t b0, uint32_t b1) {
    asm volatile(
        "mma.sync.aligned.m16n8k16.row.col.f32.f16.f16.f32 "
        "{%0,%1,%2,%3}, {%4,%5,%6,%7}, {%8,%9}, {%0,%1,%2,%3};"
        : "+f"(d[0]), "+f"(d[1]), "+f"(d[2]), "+f"(d[3])
        : "r"(a[0]), "r"(a[1]), "r"(a[2]), "r"(a[3]), "r"(b0), "r"(b1));
}

__device__ __forceinline__ void ldm4t(uint32_t& r0, uint32_t& r1, uint32_t& r2, uint32_t& r3,
                                      uint32_t addr) {
    asm volatile("ldmatrix.sync.aligned.m8n8.x4.trans.shared.b16 {%0,%1,%2,%3}, [%4];"
                 : "=r"(r0), "=r"(r1), "=r"(r2), "=r"(r3) : "r"(addr));
}

__device__ __forceinline__ void cp16s(uint32_t dst, const void* g) {
    asm volatile("cp.async.ca.shared.global [%0], [%1], 16;" :: "r"(dst), "l"(g));
}
__device__ __forceinline__ uint32_t U32(const __half* p) { return *(const uint32_t*)p; }

// ---------------- converters -------------------------------------------------
__global__ __launch_bounds__(256) void conv_x(const float4* __restrict__ in,
                                              __half2* __restrict__ out, int n4) {
    int i = blockIdx.x * 256 + threadIdx.x;
    if (i < n4) {
        float4 v = in[i];
        out[2 * i]     = __floats2half2_rn(v.x, v.y);
        out[2 * i + 1] = __floats2half2_rn(v.z, v.w);
    }
}

// W[k][n] fp32 -> out[n][k] fp16
__global__ void conv_wT(const float* __restrict__ in, __half* __restrict__ out) {
    __shared__ float tle[32][33];
    int bx = blockIdx.x * 32, by = blockIdx.y * 32;
    int tx = threadIdx.x, ty = threadIdx.y;
    #pragma unroll
    for (int i = 0; i < 4; i++)
        tle[ty + 8 * i][tx] = in[(size_t)(by + ty + 8 * i) * DM + bx + tx];
    __syncthreads();
    #pragma unroll
    for (int i = 0; i < 4; i++)
        out[(size_t)(bx + ty + 8 * i) * DM + by + tx] = __float2half_rn(tle[tx][ty + 8 * i]);
}

// ============================================================================
// fp16 GEMM: C[4096,1024] = A[M,K](half) @ Bt[N,K](half)^T
// BM=BN=128, BK=32, 3-stage cp.async. 8 warps (4m x 2n), warp tile 32x64.
// Output: half (Ch) or float+bias (Cf).
// ============================================================================
#define G_LD   40                         // halves per smem row (32 + 8 pad)
#define G_TILE (128 * G_LD)               // halves per operand per stage
#define G_SMEM (3 * 2 * G_TILE * 2)       // bytes = 61440

__global__ __launch_bounds__(256) void gemm_h(
    const __half* __restrict__ A, const __half* __restrict__ Bt,
    const float* __restrict__ bias, __half* __restrict__ Ch, float* __restrict__ Cf)
{
    extern __shared__ __align__(16) __half gsm[];
    __half* As = gsm;                     // 3 stages x 128 x 40
    __half* Bs = gsm + 3 * G_TILE;

    const int tid = threadIdx.x;
    const int lane = tid & 31, wid = tid >> 5;
    const int lr = lane >> 2, lc = lane & 3;
    const int wm = wid & 3, wn = wid >> 2;
    const int row0 = blockIdx.y * 128, col0 = blockIdx.x * 128;

    uint32_t sA = (uint32_t)__cvta_generic_to_shared(As);
    uint32_t sB = (uint32_t)__cvta_generic_to_shared(Bs);

    float acc[2][8][4];
    #pragma unroll
    for (int mt = 0; mt < 2; mt++)
        #pragma unroll
        for (int nt = 0; nt < 8; nt++)
            #pragma unroll
            for (int r = 0; r < 4; r++) acc[mt][nt][r] = 0.f;

    auto issue = [&](int t) {
        int buf = t % 3, k0 = t * 32;
        #pragma unroll
        for (int i = 0; i < 2; i++) {
            int idx = tid + i * 256;        // 0..511
            int r = idx >> 2, c = idx & 3;  // 128 rows x 4 chunks (8 halves)
            uint32_t off = (uint32_t)(buf * G_TILE + r * G_LD + c * 8) * 2;
            cp16s(sA + off, A  + (size_t)(row0 + r) * DM + k0 + c * 8);
            cp16s(sB + off, Bt + (size_t)(col0 + r) * DM + k0 + c * 8);
        }
        asm volatile("cp.async.commit_group;" ::: "memory");
    };

    issue(0); issue(1);

    const int NT = DM / 32;   // 32
    for (int it = 0; it < NT; ++it) {
        __syncthreads();
        if (it + 2 < NT) {
            issue(it + 2);
            asm volatile("cp.async.wait_group 2;" ::: "memory");
        } else if (it + 1 < NT) {
            asm volatile("cp.async.wait_group 1;" ::: "memory");
        } else {
            asm volatile("cp.async.wait_group 0;" ::: "memory");
        }
        __syncthreads();

        const __half* ab = As + (it % 3) * G_TILE;
        const __half* bb = Bs + (it % 3) * G_TILE;
        #pragma unroll
        for (int ks = 0; ks < 2; ks++) {
            uint32_t a[2][4];
            #pragma unroll
            for (int mt = 0; mt < 2; mt++) {
                const __half* ap = ab + (wm * 32 + mt * 16 + lr) * G_LD + ks * 16 + 2 * lc;
                a[mt][0] = U32(ap);
                a[mt][1] = U32(ap + 8 * G_LD);
                a[mt][2] = U32(ap + 8);
                a[mt][3] = U32(ap + 8 * G_LD + 8);
            }
            #pragma unroll
            for (int nt = 0; nt < 8; nt++) {
                const __half* bp = bb + (wn * 64 + nt * 8 + lr) * G_LD + ks * 16 + 2 * lc;
                uint32_t b0 = U32(bp), b1 = U32(bp + 8);
                mma_f16(acc[0][nt], a[0], b0, b1);
                mma_f16(acc[1][nt], a[1], b0, b1);
            }
        }
    }

    #pragma unroll
    for (int mt = 0; mt < 2; mt++) {
        int r = row0 + wm * 32 + mt * 16 + lr;
        #pragma unroll
        for (int nt = 0; nt < 8; nt++) {
            int c = col0 + wn * 64 + nt * 8 + 2 * lc;
            if (Cf) {
                float bx = bias ? bias[c] : 0.f, by = bias ? bias[c + 1] : 0.f;
                *(float2*)&Cf[(size_t)r * DM + c] =
                    make_float2(acc[mt][nt][0] + bx, acc[mt][nt][1] + by);
                *(float2*)&Cf[(size_t)(r + 8) * DM + c] =
                    make_float2(acc[mt][nt][2] + bx, acc[mt][nt][3] + by);
            } else {
                *(__half2*)&Ch[(size_t)r * DM + c] =
                    __floats2half2_rn(acc[mt][nt][0], acc[mt][nt][1]);
                *(__half2*)&Ch[(size_t)(r + 8) * DM + c] =
                    __floats2half2_rn(acc[mt][nt][2], acc[mt][nt][3]);
            }
        }
    }
}

// ============================================================================
// fp16 flash attention (causal). 128 q/CTA, 64 kv/tile, double-buffered cp.async.
// 8 warps; warp owns 16 q-rows. V fragments via ldmatrix.x4.trans (no transpose).
// ============================================================================
#define F_LD   72                          // halves per row (64 + 8)
#define F_QP   (128 * F_LD)                // Qs / Ps halves
#define F_KV   (64 * F_LD)                 // per K/V buffer halves
#define F_SMEM ((F_QP + 2 * F_KV + 2 * F_KV + F_QP) * 2)   // 73728 B

__global__ __launch_bounds__(256) void flash_h(
    const __half* __restrict__ Q, const __half* __restrict__ K,
    const __half* __restrict__ V, __half* __restrict__ O)
{
    extern __shared__ __align__(16) __half fsm[];
    __half* Qs = fsm;                      // [128][72]
    __half* Ks = Qs + F_QP;                // 2 x [64][72]
    __half* Vs = Ks + 2 * F_KV;            // 2 x [64][72] (row-major [kk][d])
    __half* Ps = Vs + 2 * F_KV;            // [128][72]

    const int tid = threadIdx.x;
    const int lane = tid & 31, wid = tid >> 5;
    const int lr = lane >> 2, lc = lane & 3;
    const int q0 = blockIdx.x * 128;
    const int h = blockIdx.y, b = blockIdx.z;

    const __half* Qg = Q + (size_t)(b * CTX) * DM + h * HD;
    const __half* Kg = K + (size_t)(b * CTX) * DM + h * HD;
    const __half* Vg = V + (size_t)(b * CTX) * DM + h * HD;

    uint32_t sQ = (uint32_t)__cvta_generic_to_shared(Qs);
    uint32_t sK = (uint32_t)__cvta_generic_to_shared(Ks);
    uint32_t sV = (uint32_t)__cvta_generic_to_shared(Vs);

    auto issueKV = [&](int t, int buf) {
        int kb = t * 64;
        #pragma unroll
        for (int i = 0; i < 4; i++) {
            int idx = tid + i * 256;            // 0..1023
            int sel = idx >> 9;                 // 0: K, 1: V
            int kk = (idx >> 3) & 63, c = idx & 7;
            const __half* src = (sel ? Vg : Kg) + (size_t)(kb + kk) * DM + c * 8;
            uint32_t dst = (sel ? sV : sK) + (uint32_t)(buf * F_KV + kk * F_LD + c * 8) * 2;
            cp16s(dst, src);
        }
        asm volatile("cp.async.commit_group;" ::: "memory");
    };

    // prologue: Q tile + KV tile 0 in one group
    #pragma unroll
    for (int i = 0; i < 4; i++) {
        int idx = tid + i * 256;                // 0..1023
        int q = idx >> 3, c = idx & 7;
        cp16s(sQ + (uint32_t)(q * F_LD + c * 8) * 2, Qg + (size_t)(q0 + q) * DM + c * 8);
    }
    issueKV(0, 0);

    float m0 = -INFINITY, m1 = -INFINITY, l0 = 0.f, l1 = 0.f;
    float o[8][4];
    #pragma unroll
    for (int dt = 0; dt < 8; dt++)
        #pragma unroll
        for (int r = 0; r < 4; r++) o[dt][r] = 0.f;

    const int qw = wid * 16;       // warp's q-row base within tile
    const int vrow = lane & 15;    // ldmatrix row select
    const int vblk = lane >> 4;    // ldmatrix col-block select

    const int nkv = q0 / 64 + 2;
    for (int t = 0; t < nkv; ++t) {
        __syncthreads();  // all warps done with buffer (t+1)&1 from iteration t-1
        if (t + 1 < nkv) {
            issueKV(t + 1, (t + 1) & 1);
            asm volatile("cp.async.wait_group 1;" ::: "memory");
        } else {
            asm volatile("cp.async.wait_group 0;" ::: "memory");
        }
        __syncthreads();

        const __half* kb_ = Ks + (t & 1) * F_KV;
        uint32_t vb32 = sV + (uint32_t)((t & 1) * F_KV) * 2;

        // ---- S = Q @ K^T (warp: 16 x 64) ----
        float s[8][4];
        #pragma unroll
        for (int nt = 0; nt < 8; nt++)
            #pragma unroll
            for (int r = 0; r < 4; r++) s[nt][r] = 0.f;

        #pragma unroll
        for (int ks = 0; ks < 4; ks++) {
            uint32_t a[4];
            const __half* qp = Qs + (qw + lr) * F_LD + ks * 16 + 2 * lc;
            a[0] = U32(qp);
            a[1] = U32(qp + 8 * F_LD);
            a[2] = U32(qp + 8);
            a[3] = U32(qp + 8 * F_LD + 8);
            #pragma unroll
            for (int nt = 0; nt < 8; nt++) {
                const __half* kp = kb_ + (nt * 8 + lr) * F_LD + ks * 16 + 2 * lc;
                mma_f16(s[nt], a, U32(kp), U32(kp + 8));
            }
        }

        // scale
        #pragma unroll
        for (int nt = 0; nt < 8; nt++)
            #pragma unroll
            for (int r = 0; r < 4; r++) s[nt][r] *= 0.125f;

        const int kb = t * 64;
        const int r0 = q0 + qw + lr, r1 = r0 + 8;

        // causal mask (diagonal tiles only)
        if (kb + 63 > q0) {
            #pragma unroll
            for (int nt = 0; nt < 8; nt++) {
                #pragma unroll
                for (int j = 0; j < 2; j++) {
                    int key = kb + nt * 8 + 2 * lc + j;
                    if (key > r0) s[nt][j]     = -1e30f;
                    if (key > r1) s[nt][2 + j] = -1e30f;
                }
            }
        }

        // ---- online softmax ----
        float rm0 = -1e30f, rm1 = -1e30f;
        #pragma unroll
        for (int nt = 0; nt < 8; nt++) {
            rm0 = fmaxf(rm0, fmaxf(s[nt][0], s[nt][1]));
            rm1 = fmaxf(rm1, fmaxf(s[nt][2], s[nt][3]));
        }
        rm0 = fmaxf(rm0, __shfl_xor_sync(0xffffffffu, rm0, 1));
        rm0 = fmaxf(rm0, __shfl_xor_sync(0xffffffffu, rm0, 2));
        rm1 = fmaxf(rm1, __shfl_xor_sync(0xffffffffu, rm1, 1));
        rm1 = fmaxf(rm1, __shfl_xor_sync(0xffffffffu, rm1, 2));

        float mn0 = fmaxf(m0, rm0), mn1 = fmaxf(m1, rm1);
        float c0 = __expf(m0 - mn0), c1 = __expf(m1 - mn1);
        float rs0 = 0.f, rs1 = 0.f;
        #pragma unroll
        for (int nt = 0; nt < 8; nt++) {
            s[nt][0] = __expf(s[nt][0] - mn0);
            s[nt][1] = __expf(s[nt][1] - mn0);
            s[nt][2] = __expf(s[nt][2] - mn1);
            s[nt][3] = __expf(s[nt][3] - mn1);
            rs0 += s[nt][0] + s[nt][1];
            rs1 += s[nt][2] + s[nt][3];
        }
        rs0 += __shfl_xor_sync(0xffffffffu, rs0, 1);
        rs0 += __shfl_xor_sync(0xffffffffu, rs0, 2);
        rs1 += __shfl_xor_sync(0xffffffffu, rs1, 1);
        rs1 += __shfl_xor_sync(0xffffffffu, rs1, 2);

        l0 = l0 * c0 + rs0; m0 = mn0;
        l1 = l1 * c1 + rs1; m1 = mn1;
        #pragma unroll
        for (int dt = 0; dt < 8; dt++) {
            o[dt][0] *= c0; o[dt][1] *= c0;
            o[dt][2] *= c1; o[dt][3] *= c1;
        }

        // ---- P -> smem (fp16) ----
        #pragma unroll
        for (int nt = 0; nt < 8; nt++) {
            *(__half2*)&Ps[(qw + lr) * F_LD + nt * 8 + 2 * lc] =
                __floats2half2_rn(s[nt][0], s[nt][1]);
            *(__half2*)&Ps[(qw + lr + 8) * F_LD + nt * 8 + 2 * lc] =
                __floats2half2_rn(s[nt][2], s[nt][3]);
        }
        __syncwarp();

        // ---- O += P @ V (V frags via ldmatrix.trans) ----
        #pragma unroll
        for (int ks = 0; ks < 4; ks++) {
            uint32_t a[4];
            const __half* pp = Ps + (qw + lr) * F_LD + ks * 16 + 2 * lc;
            a[0] = U32(pp);
            a[1] = U32(pp + 8 * F_LD);
            a[2] = U32(pp + 8);
            a[3] = U32(pp + 8 * F_LD + 8);
            #pragma unroll
            for (int ntp = 0; ntp < 4; ntp++) {
                uint32_t b0, b1, b2, b3;
                uint32_t addr = vb32 +
                    (uint32_t)((ks * 16 + vrow) * F_LD + (2 * ntp + vblk) * 8) * 2;
                ldm4t(b0, b1, b2, b3, addr);
                mma_f16(o[2 * ntp],     a, b0, b1);
                mma_f16(o[2 * ntp + 1], a, b2, b3);
            }
        }
    }

    // ---- normalize + write ctx (fp16) ----
    float i0 = 1.f / l0, i1 = 1.f / l1;
    const int r0 = q0 + qw + lr;
    __half* Og = O + (size_t)(b * CTX) * DM + h * HD;
    #pragma unroll
    for (int dt = 0; dt < 8; dt++) {
        int c = dt * 8 + 2 * lc;
        *(__half2*)&Og[(size_t)r0 * DM + c] =
            __floats2half2_rn(o[dt][0] * i0, o[dt][1] * i0);
        *(__half2*)&Og[(size_t)(r0 + 8) * DM + c] =
            __floats2half2_rn(o[dt][2] * i1, o[dt][3] * i1);
    }
}

// ============================================================================
// launch
// ============================================================================
extern "C" void kernel_launch(void* const* d_in, const int* in_sizes, int n_in,
                              void* d_out, int out_size)
{
    const float* x  = (const float*)d_in[0];
    const float* Wq = (const float*)d_in[1];
    const float* Wk = (const float*)d_in[2];
    const float* Wv = (const float*)d_in[3];
    const float* Wo = (const float*)d_in[4];
    const float* bo = (const float*)d_in[5];
    float* out = (float*)d_out;

    __half *Xh, *Wh, *Qh, *Kh, *Vh, *Ch;
    cudaGetSymbolAddress((void**)&Xh, g_Xh);
    cudaGetSymbolAddress((void**)&Wh, g_Wh);
    cudaGetSymbolAddress((void**)&Qh, g_Qh);
    cudaGetSymbolAddress((void**)&Kh, g_Kh);
    cudaGetSymbolAddress((void**)&Vh, g_Vh);
    cudaGetSymbolAddress((void**)&Ch, g_Ch);

    cudaFuncSetAttribute(gemm_h, cudaFuncAttributeMaxDynamicSharedMemorySize, G_SMEM);
    cudaFuncSetAttribute(flash_h, cudaFuncAttributeMaxDynamicSharedMemorySize, F_SMEM);

    const int NX4 = BT * DM / 4;
    conv_x<<<NX4 / 256, 256>>>((const float4*)x, (__half2*)Xh, NX4);

    dim3 tgrid(DM / 32, DM / 32), tblk(32, 8);
    conv_wT<<<tgrid, tblk>>>(Wq, Wh + 0 * DM * DM);
    conv_wT<<<tgrid, tblk>>>(Wk, Wh + 1 * DM * DM);
    conv_wT<<<tgrid, tblk>>>(Wv, Wh + 2 * DM * DM);
    conv_wT<<<tgrid, tblk>>>(Wo, Wh + 3 * DM * DM);

    dim3 ggrid(DM / 128, BT / 128);   // (8, 32)
    gemm_h<<<ggrid, 256, G_SMEM>>>(Xh, Wh + 0 * DM * DM, nullptr, Qh, nullptr);
    gemm_h<<<ggrid, 256, G_SMEM>>>(Xh, Wh + 1 * DM * DM, nullptr, Kh, nullptr);
    gemm_h<<<ggrid, 256, G_SMEM>>>(Xh, Wh + 2 * DM * DM, nullptr, Vh, nullptr);

    dim3 fgrid(CTX / 128, NH, BATCH);  // (16, 16, 2)
    flash_h<<<fgrid, 256, F_SMEM>>>(Qh, Kh, Vh, Ch);

    gemm_h<<<ggrid, 256, G_SMEM>>>(Ch, Wh + 3 * DM * DM, bo, nullptr, out);
}

// round 6
// speedup vs baseline: 1.8564x; 1.0802x over previous
#include <cuda_runtime.h>
#include <cuda_fp16.h>
#include <math.h>
#include <stdint.h>

#define BATCH 2
#define CTX   2048
#define DM    1024
#define NH    16
#define HD    64
#define BT    (BATCH*CTX)   // 4096

// ---------------- scratch (device globals; no allocation allowed) ----------
__device__ __half g_Xh[BT * DM];
__device__ __half g_Wh[4 * DM * DM];   // transposed weights [N][K], fp16
__device__ __half g_Qh[BT * DM];
__device__ __half g_Kh[BT * DM];
__device__ __half g_Vh[BT * DM];
__device__ __half g_Ch[BT * DM];

// Q projections are pre-scaled by 1/sqrt(64) * log2(e) so flash works in exp2 domain
#define QSCALE 0.18033688011112042f

// ---------------- helpers ---------------------------------------------------
__device__ __forceinline__ void mma_f16(float* d, const uint32_t* a, uint32_t b0, uint32_t b1) {
    asm volatile(
        "mma.sync.aligned.m16n8k16.row.col.f32.f16.f16.f32 "
        "{%0,%1,%2,%3}, {%4,%5,%6,%7}, {%8,%9}, {%0,%1,%2,%3};"
        : "+f"(d[0]), "+f"(d[1]), "+f"(d[2]), "+f"(d[3])
        : "r"(a[0]), "r"(a[1]), "r"(a[2]), "r"(a[3]), "r"(b0), "r"(b1));
}

__device__ __forceinline__ void ldm4t(uint32_t& r0, uint32_t& r1, uint32_t& r2, uint32_t& r3,
                                      uint32_t addr) {
    asm volatile("ldmatrix.sync.aligned.m8n8.x4.trans.shared.b16 {%0,%1,%2,%3}, [%4];"
                 : "=r"(r0), "=r"(r1), "=r"(r2), "=r"(r3) : "r"(addr));
}

__device__ __forceinline__ void cp16s(uint32_t dst, const void* g) {
    asm volatile("cp.async.ca.shared.global [%0], [%1], 16;" :: "r"(dst), "l"(g));
}
__device__ __forceinline__ uint32_t U32(const __half* p) { return *(const uint32_t*)p; }
__device__ __forceinline__ uint32_t packh2(float x, float y) {
    __half2 h = __floats2half2_rn(x, y);
    return *(uint32_t*)&h;
}

// ---------------- converters -------------------------------------------------
__global__ __launch_bounds__(256) void conv_x(const float4* __restrict__ in,
                                              __half2* __restrict__ out, int n4) {
    int i = blockIdx.x * 256 + threadIdx.x;
    if (i < n4) {
        float4 v = in[i];
        out[2 * i]     = __floats2half2_rn(v.x, v.y);
        out[2 * i + 1] = __floats2half2_rn(v.z, v.w);
    }
}

// W[k][n] fp32 -> out[n][k] fp16  (4 matrices via blockIdx.z)
__global__ void conv_wT(const float* const* __restrict__ srcs, __half* __restrict__ out) {
    __shared__ float tle[32][33];
    const float* in = srcs[blockIdx.z];
    __half* o = out + (size_t)blockIdx.z * DM * DM;
    int bx = blockIdx.x * 32, by = blockIdx.y * 32;
    int tx = threadIdx.x, ty = threadIdx.y;
    #pragma unroll
    for (int i = 0; i < 4; i++)
        tle[ty + 8 * i][tx] = in[(size_t)(by + ty + 8 * i) * DM + bx + tx];
    __syncthreads();
    #pragma unroll
    for (int i = 0; i < 4; i++)
        o[(size_t)(bx + ty + 8 * i) * DM + by + tx] = __float2half_rn(tle[tx][ty + 8 * i]);
}
__device__ const float* g_wsrc[4];

// ============================================================================
// fp16 GEMM body (shared by QKV-fused and out-proj kernels)
// BM=BN=128, BK=32, 3-stage cp.async. 8 warps (4m x 2n), warp tile 32x64.
// ============================================================================
#define G_LD   40
#define G_TILE (128 * G_LD)
#define G_SMEM (3 * 2 * G_TILE * 2)       // 61440 B

struct GemmAcc { float a[2][8][4]; };

__device__ __forceinline__ void gemm_core(
    const __half* __restrict__ A, const __half* __restrict__ Bt,
    int row0, int col0, GemmAcc& acc, __half* gsm)
{
    __half* As = gsm;
    __half* Bs = gsm + 3 * G_TILE;
    const int tid = threadIdx.x;
    const int lane = tid & 31, wid = tid >> 5;
    const int lr = lane >> 2, lc = lane & 3;
    const int wm = wid & 3, wn = wid >> 2;

    uint32_t sA = (uint32_t)__cvta_generic_to_shared(As);
    uint32_t sB = (uint32_t)__cvta_generic_to_shared(Bs);

    #pragma unroll
    for (int mt = 0; mt < 2; mt++)
        #pragma unroll
        for (int nt = 0; nt < 8; nt++)
            #pragma unroll
            for (int r = 0; r < 4; r++) acc.a[mt][nt][r] = 0.f;

    auto issue = [&](int t) {
        int buf = t % 3, k0 = t * 32;
        #pragma unroll
        for (int i = 0; i < 2; i++) {
            int idx = tid + i * 256;
            int r = idx >> 2, c = idx & 3;
            uint32_t off = (uint32_t)(buf * G_TILE + r * G_LD + c * 8) * 2;
            cp16s(sA + off, A  + (size_t)(row0 + r) * DM + k0 + c * 8);
            cp16s(sB + off, Bt + (size_t)(col0 + r) * DM + k0 + c * 8);
        }
        asm volatile("cp.async.commit_group;" ::: "memory");
    };

    issue(0); issue(1);
    const int NT = DM / 32;
    for (int it = 0; it < NT; ++it) {
        __syncthreads();
        if (it + 2 < NT) {
            issue(it + 2);
            asm volatile("cp.async.wait_group 2;" ::: "memory");
        } else if (it + 1 < NT) {
            asm volatile("cp.async.wait_group 1;" ::: "memory");
        } else {
            asm volatile("cp.async.wait_group 0;" ::: "memory");
        }
        __syncthreads();

        const __half* ab = As + (it % 3) * G_TILE;
        const __half* bb = Bs + (it % 3) * G_TILE;
        #pragma unroll
        for (int ks = 0; ks < 2; ks++) {
            uint32_t a[2][4];
            #pragma unroll
            for (int mt = 0; mt < 2; mt++) {
                const __half* ap = ab + (wm * 32 + mt * 16 + lr) * G_LD + ks * 16 + 2 * lc;
                a[mt][0] = U32(ap);
                a[mt][1] = U32(ap + 8 * G_LD);
                a[mt][2] = U32(ap + 8);
                a[mt][3] = U32(ap + 8 * G_LD + 8);
            }
            #pragma unroll
            for (int nt = 0; nt < 8; nt++) {
                const __half* bp = bb + (wn * 64 + nt * 8 + lr) * G_LD + ks * 16 + 2 * lc;
                uint32_t b0 = U32(bp), b1 = U32(bp + 8);
                mma_f16(acc.a[0][nt], a[0], b0, b1);
                mma_f16(acc.a[1][nt], a[1], b0, b1);
            }
        }
    }
}

// Fused QKV: grid (24, 32). mat = bx>>3 selects weight + destination.
__global__ __launch_bounds__(256) void gemm_qkv(
    const __half* __restrict__ A, const __half* __restrict__ W,
    __half* __restrict__ Qh, __half* __restrict__ Kh, __half* __restrict__ Vh)
{
    extern __shared__ __align__(16) __half gsm[];
    const int mat = blockIdx.x >> 3;
    const int col0 = (blockIdx.x & 7) * 128;
    const int row0 = blockIdx.y * 128;
    const __half* Bt = W + (size_t)mat * DM * DM;
    __half* C = (mat == 0) ? Qh : (mat == 1) ? Kh : Vh;
    const float sc = (mat == 0) ? QSCALE : 1.f;

    GemmAcc acc;
    gemm_core(A, Bt, row0, col0, acc, gsm);

    const int lane = threadIdx.x & 31, wid = threadIdx.x >> 5;
    const int lr = lane >> 2, lc = lane & 3;
    const int wm = wid & 3, wn = wid >> 2;
    #pragma unroll
    for (int mt = 0; mt < 2; mt++) {
        int r = row0 + wm * 32 + mt * 16 + lr;
        #pragma unroll
        for (int nt = 0; nt < 8; nt++) {
            int c = col0 + wn * 64 + nt * 8 + 2 * lc;
            *(__half2*)&C[(size_t)r * DM + c] =
                __floats2half2_rn(acc.a[mt][nt][0] * sc, acc.a[mt][nt][1] * sc);
            *(__half2*)&C[(size_t)(r + 8) * DM + c] =
                __floats2half2_rn(acc.a[mt][nt][2] * sc, acc.a[mt][nt][3] * sc);
        }
    }
}

// Out projection: fp32 output + bias
__global__ __launch_bounds__(256) void gemm_out(
    const __half* __restrict__ A, const __half* __restrict__ Bt,
    const float* __restrict__ bias, float* __restrict__ Cf)
{
    extern __shared__ __align__(16) __half gsm[];
    const int col0 = blockIdx.x * 128, row0 = blockIdx.y * 128;

    GemmAcc acc;
    gemm_core(A, Bt, row0, col0, acc, gsm);

    const int lane = threadIdx.x & 31, wid = threadIdx.x >> 5;
    const int lr = lane >> 2, lc = lane & 3;
    const int wm = wid & 3, wn = wid >> 2;
    #pragma unroll
    for (int mt = 0; mt < 2; mt++) {
        int r = row0 + wm * 32 + mt * 16 + lr;
        #pragma unroll
        for (int nt = 0; nt < 8; nt++) {
            int c = col0 + wn * 64 + nt * 8 + 2 * lc;
            float bx = bias[c], by = bias[c + 1];
            *(float2*)&Cf[(size_t)r * DM + c] =
                make_float2(acc.a[mt][nt][0] + bx, acc.a[mt][nt][1] + by);
            *(float2*)&Cf[(size_t)(r + 8) * DM + c] =
                make_float2(acc.a[mt][nt][2] + bx, acc.a[mt][nt][3] + by);
        }
    }
}

// ============================================================================
// fp16 flash attention (causal, exp2 domain). 128 q/CTA, 64 kv/tile.
// 3-buffer cp.async pipeline, ONE sync per tile. P kept in registers.
// ============================================================================
#define F_LD   72
#define F_QP   (128 * F_LD)
#define F_KV   (64 * F_LD)
#define F_SMEM ((F_QP + 3 * F_KV + 3 * F_KV) * 2)   // 73728 B

__global__ __launch_bounds__(256) void flash_h(
    const __half* __restrict__ Q, const __half* __restrict__ K,
    const __half* __restrict__ V, __half* __restrict__ O)
{
    extern __shared__ __align__(16) __half fsm[];
    __half* Qs = fsm;                      // [128][72]
    __half* Ks = Qs + F_QP;                // 3 x [64][72]
    __half* Vs = Ks + 3 * F_KV;            // 3 x [64][72]

    const int tid = threadIdx.x;
    const int lane = tid & 31, wid = tid >> 5;
    const int lr = lane >> 2, lc = lane & 3;
    const int q0 = (gridDim.x - 1 - blockIdx.x) * 128;   // heavy tiles first
    const int h = blockIdx.y, b = blockIdx.z;

    const __half* Qg = Q + (size_t)(b * CTX) * DM + h * HD;
    const __half* Kg = K + (size_t)(b * CTX) * DM + h * HD;
    const __half* Vg = V + (size_t)(b * CTX) * DM + h * HD;

    uint32_t sQ = (uint32_t)__cvta_generic_to_shared(Qs);
    uint32_t sK = (uint32_t)__cvta_generic_to_shared(Ks);
    uint32_t sV = (uint32_t)__cvta_generic_to_shared(Vs);

    auto issueKV = [&](int t) {
        int kb = t * 64, buf = t % 3;
        #pragma unroll
        for (int i = 0; i < 4; i++) {
            int idx = tid + i * 256;
            int sel = idx >> 9;
            int kk = (idx >> 3) & 63, c = idx & 7;
            const __half* src = (sel ? Vg : Kg) + (size_t)(kb + kk) * DM + c * 8;
            uint32_t dst = (sel ? sV : sK) + (uint32_t)(buf * F_KV + kk * F_LD + c * 8) * 2;
            cp16s(dst, src);
        }
        asm volatile("cp.async.commit_group;" ::: "memory");
    };

    const int nkv = q0 / 64 + 2;

    // prologue: Q tile joins tile-0's commit group
    #pragma unroll
    for (int i = 0; i < 4; i++) {
        int idx = tid + i * 256;
        int q = idx >> 3, c = idx & 7;
        cp16s(sQ + (uint32_t)(q * F_LD + c * 8) * 2, Qg + (size_t)(q0 + q) * DM + c * 8);
    }
    issueKV(0);
    issueKV(1);

    float m0 = -INFINITY, m1 = -INFINITY, l0 = 0.f, l1 = 0.f;
    float o[8][4];
    #pragma unroll
    for (int dt = 0; dt < 8; dt++)
        #pragma unroll
        for (int r = 0; r < 4; r++) o[dt][r] = 0.f;

    const int qw = wid * 16;
    const int vrow = lane & 15;
    const int vblk = lane >> 4;

    for (int t = 0; t < nkv; ++t) {
        __syncthreads();   // all warps done computing tile t-1 => buf (t+2)%3 reusable
        if (t + 2 < nkv) {
            issueKV(t + 2);
            asm volatile("cp.async.wait_group 2;" ::: "memory");
        } else if (t + 1 < nkv) {
            asm volatile("cp.async.wait_group 1;" ::: "memory");
        } else {
            asm volatile("cp.async.wait_group 0;" ::: "memory");
        }
        __syncthreads();   // loaded data visible to all warps

        const __half* kb_ = Ks + (t % 3) * F_KV;
        uint32_t vb32 = sV + (uint32_t)((t % 3) * F_KV) * 2;

        // ---- S = Q @ K^T (warp: 16 x 64), already in log2 domain ----
        float s[8][4];
        #pragma unroll
        for (int nt = 0; nt < 8; nt++)
            #pragma unroll
            for (int r = 0; r < 4; r++) s[nt][r] = 0.f;

        #pragma unroll
        for (int ks = 0; ks < 4; ks++) {
            uint32_t a[4];
            const __half* qp = Qs + (qw + lr) * F_LD + ks * 16 + 2 * lc;
            a[0] = U32(qp);
            a[1] = U32(qp + 8 * F_LD);
            a[2] = U32(qp + 8);
            a[3] = U32(qp + 8 * F_LD + 8);
            #pragma unroll
            for (int nt = 0; nt < 8; nt++) {
                const __half* kp = kb_ + (nt * 8 + lr) * F_LD + ks * 16 + 2 * lc;
                mma_f16(s[nt], a, U32(kp), U32(kp + 8));
            }
        }

        const int kb = t * 64;
        const int r0 = q0 + qw + lr, r1 = r0 + 8;

        if (kb + 63 > q0) {
            #pragma unroll
            for (int nt = 0; nt < 8; nt++) {
                #pragma unroll
                for (int j = 0; j < 2; j++) {
                    int key = kb + nt * 8 + 2 * lc + j;
                    if (key > r0) s[nt][j]     = -1e30f;
                    if (key > r1) s[nt][2 + j] = -1e30f;
                }
            }
        }

        // ---- online softmax (exp2 domain) ----
        float rm0 = -1e30f, rm1 = -1e30f;
        #pragma unroll
        for (int nt = 0; nt < 8; nt++) {
            rm0 = fmaxf(rm0, fmaxf(s[nt][0], s[nt][1]));
            rm1 = fmaxf(rm1, fmaxf(s[nt][2], s[nt][3]));
        }
        rm0 = fmaxf(rm0, __shfl_xor_sync(0xffffffffu, rm0, 1));
        rm0 = fmaxf(rm0, __shfl_xor_sync(0xffffffffu, rm0, 2));
        rm1 = fmaxf(rm1, __shfl_xor_sync(0xffffffffu, rm1, 1));
        rm1 = fmaxf(rm1, __shfl_xor_sync(0xffffffffu, rm1, 2));

        float mn0 = fmaxf(m0, rm0), mn1 = fmaxf(m1, rm1);
        float c0 = exp2f(m0 - mn0), c1 = exp2f(m1 - mn1);
        float rs0 = 0.f, rs1 = 0.f;
        #pragma unroll
        for (int nt = 0; nt < 8; nt++) {
            s[nt][0] = exp2f(s[nt][0] - mn0);
            s[nt][1] = exp2f(s[nt][1] - mn0);
            s[nt][2] = exp2f(s[nt][2] - mn1);
            s[nt][3] = exp2f(s[nt][3] - mn1);
            rs0 += s[nt][0] + s[nt][1];
            rs1 += s[nt][2] + s[nt][3];
        }
        rs0 += __shfl_xor_sync(0xffffffffu, rs0, 1);
        rs0 += __shfl_xor_sync(0xffffffffu, rs0, 2);
        rs1 += __shfl_xor_sync(0xffffffffu, rs1, 1);
        rs1 += __shfl_xor_sync(0xffffffffu, rs1, 2);

        l0 = l0 * c0 + rs0; m0 = mn0;
        l1 = l1 * c1 + rs1; m1 = mn1;
        #pragma unroll
        for (int dt = 0; dt < 8; dt++) {
            o[dt][0] *= c0; o[dt][1] *= c0;
            o[dt][2] *= c1; o[dt][3] *= c1;
        }

        // ---- O += P @ V : P packed from registers (C-frag == A-frag layout) ----
        #pragma unroll
        for (int ks = 0; ks < 4; ks++) {
            uint32_t a[4];
            a[0] = packh2(s[2 * ks][0],     s[2 * ks][1]);
            a[1] = packh2(s[2 * ks][2],     s[2 * ks][3]);
            a[2] = packh2(s[2 * ks + 1][0], s[2 * ks + 1][1]);
            a[3] = packh2(s[2 * ks + 1][2], s[2 * ks + 1][3]);
            #pragma unroll
            for (int ntp = 0; ntp < 4; ntp++) {
                uint32_t b0, b1, b2, b3;
                uint32_t addr = vb32 +
                    (uint32_t)((ks * 16 + vrow) * F_LD + (2 * ntp + vblk) * 8) * 2;
                ldm4t(b0, b1, b2, b3, addr);
                mma_f16(o[2 * ntp],     a, b0, b1);
                mma_f16(o[2 * ntp + 1], a, b2, b3);
            }
        }
    }

    // ---- normalize + write ctx (fp16) ----
    float i0 = 1.f / l0, i1 = 1.f / l1;
    const int r0 = q0 + qw + lr;
    __half* Og = O + (size_t)(b * CTX) * DM + h * HD;
    #pragma unroll
    for (int dt = 0; dt < 8; dt++) {
        int c = dt * 8 + 2 * lc;
        *(__half2*)&Og[(size_t)r0 * DM + c] =
            __floats2half2_rn(o[dt][0] * i0, o[dt][1] * i0);
        *(__half2*)&Og[(size_t)(r0 + 8) * DM + c] =
            __floats2half2_rn(o[dt][2] * i1, o[dt][3] * i1);
    }
}

// ---- tiny kernel to publish weight source pointers (graph-capturable) ----
__global__ void set_wsrc(const float* wq, const float* wk, const float* wv, const float* wo) {
    g_wsrc[0] = wq; g_wsrc[1] = wk; g_wsrc[2] = wv; g_wsrc[3] = wo;
}

// ============================================================================
// launch
// ============================================================================
extern "C" void kernel_launch(void* const* d_in, const int* in_sizes, int n_in,
                              void* d_out, int out_size)
{
    const float* x  = (const float*)d_in[0];
    const float* Wq = (const float*)d_in[1];
    const float* Wk = (const float*)d_in[2];
    const float* Wv = (const float*)d_in[3];
    const float* Wo = (const float*)d_in[4];
    const float* bo = (const float*)d_in[5];
    float* out = (float*)d_out;

    __half *Xh, *Wh, *Qh, *Kh, *Vh, *Ch;
    cudaGetSymbolAddress((void**)&Xh, g_Xh);
    cudaGetSymbolAddress((void**)&Wh, g_Wh);
    cudaGetSymbolAddress((void**)&Qh, g_Qh);
    cudaGetSymbolAddress((void**)&Kh, g_Kh);
    cudaGetSymbolAddress((void**)&Vh, g_Vh);
    cudaGetSymbolAddress((void**)&Ch, g_Ch);
    const float** wsrc;
    cudaGetSymbolAddress((void**)&wsrc, g_wsrc);

    cudaFuncSetAttribute(gemm_qkv, cudaFuncAttributeMaxDynamicSharedMemorySize, G_SMEM);
    cudaFuncSetAttribute(gemm_out, cudaFuncAttributeMaxDynamicSharedMemorySize, G_SMEM);
    cudaFuncSetAttribute(flash_h, cudaFuncAttributeMaxDynamicSharedMemorySize, F_SMEM);

    const int NX4 = BT * DM / 4;
    conv_x<<<NX4 / 256, 256>>>((const float4*)x, (__half2*)Xh, NX4);

    set_wsrc<<<1, 1>>>(Wq, Wk, Wv, Wo);
    dim3 tgrid(DM / 32, DM / 32, 4), tblk(32, 8);
    conv_wT<<<tgrid, tblk>>>(wsrc, Wh);

    dim3 qgrid(24, BT / 128);          // fused QKV
    gemm_qkv<<<qgrid, 256, G_SMEM>>>(Xh, Wh, Qh, Kh, Vh);

    dim3 fgrid(CTX / 128, NH, BATCH);  // (16, 16, 2)
    flash_h<<<fgrid, 256, F_SMEM>>>(Qh, Kh, Vh, Ch);

    dim3 ogrid(DM / 128, BT / 128);
    gemm_out<<<ogrid, 256, G_SMEM>>>(Ch, Wh + 3 * (size_t)DM * DM, bo, out);
}

// round 7
// speedup vs baseline: 2.1922x; 1.1809x over previous
#include <cuda_runtime.h>
#include <cuda_fp16.h>
#include <math.h>
#include <stdint.h>

#define BATCH 2
#define CTX   2048
#define DM    1024
#define NH    16
#define HD    64
#define BT    (BATCH*CTX)   // 4096

// ---------------- scratch (device globals; no allocation allowed) ----------
__device__ __half g_Xh[BT * DM];
__device__ __half g_Wh[4 * DM * DM];   // transposed weights [N][K], fp16
__device__ __half g_Qh[BT * DM];
__device__ __half g_Kh[BT * DM];
__device__ __half g_Vh[BT * DM];
__device__ __half g_Ch[BT * DM];

// Q projections pre-scaled by 1/sqrt(64) * log2(e): flash works in exp2 domain
#define QSCALE 0.18033688011112042f

// ---------------- helpers ---------------------------------------------------
__device__ __forceinline__ void mma_f16(float* d, const uint32_t* a, uint32_t b0, uint32_t b1) {
    asm volatile(
        "mma.sync.aligned.m16n8k16.row.col.f32.f16.f16.f32 "
        "{%0,%1,%2,%3}, {%4,%5,%6,%7}, {%8,%9}, {%0,%1,%2,%3};"
        : "+f"(d[0]), "+f"(d[1]), "+f"(d[2]), "+f"(d[3])
        : "r"(a[0]), "r"(a[1]), "r"(a[2]), "r"(a[3]), "r"(b0), "r"(b1));
}

__device__ __forceinline__ void ldm4(uint32_t* r, uint32_t addr) {
    asm volatile("ldmatrix.sync.aligned.m8n8.x4.shared.b16 {%0,%1,%2,%3}, [%4];"
                 : "=r"(r[0]), "=r"(r[1]), "=r"(r[2]), "=r"(r[3]) : "r"(addr));
}
__device__ __forceinline__ void ldm4t(uint32_t& r0, uint32_t& r1, uint32_t& r2, uint32_t& r3,
                                      uint32_t addr) {
    asm volatile("ldmatrix.sync.aligned.m8n8.x4.trans.shared.b16 {%0,%1,%2,%3}, [%4];"
                 : "=r"(r0), "=r"(r1), "=r"(r2), "=r"(r3) : "r"(addr));
}

__device__ __forceinline__ void cp16s(uint32_t dst, const void* g) {
    asm volatile("cp.async.ca.shared.global [%0], [%1], 16;" :: "r"(dst), "l"(g));
}
__device__ __forceinline__ void cp_commit() {
    asm volatile("cp.async.commit_group;" ::: "memory");
}
__device__ __forceinline__ uint32_t packh2(float x, float y) {
    __half2 h = __floats2half2_rn(x, y);
    return *(uint32_t*)&h;
}
__device__ __forceinline__ float ex2(float x) {
    float y; asm("ex2.approx.f32 %0, %1;" : "=f"(y) : "f"(x)); return y;
}

// ---------------- converters -------------------------------------------------
__global__ __launch_bounds__(256) void conv_x(const float4* __restrict__ in,
                                              __half2* __restrict__ out, int n4) {
    int i = blockIdx.x * 256 + threadIdx.x;
    if (i < n4) {
        float4 v = in[i];
        out[2 * i]     = __floats2half2_rn(v.x, v.y);
        out[2 * i + 1] = __floats2half2_rn(v.z, v.w);
    }
}

__device__ const float* g_wsrc[4];
// W[k][n] fp32 -> out[n][k] fp16  (4 matrices via blockIdx.z)
__global__ void conv_wT(const float* const* __restrict__ srcs, __half* __restrict__ out) {
    __shared__ float tle[32][33];
    const float* in = srcs[blockIdx.z];
    __half* o = out + (size_t)blockIdx.z * DM * DM;
    int bx = blockIdx.x * 32, by = blockIdx.y * 32;
    int tx = threadIdx.x, ty = threadIdx.y;
    #pragma unroll
    for (int i = 0; i < 4; i++)
        tle[ty + 8 * i][tx] = in[(size_t)(by + ty + 8 * i) * DM + bx + tx];
    __syncthreads();
    #pragma unroll
    for (int i = 0; i < 4; i++)
        o[(size_t)(bx + ty + 8 * i) * DM + by + tx] = __float2half_rn(tle[tx][ty + 8 * i]);
}

// ============================================================================
// fp16 GEMM core. BM=BN=128, BK=32, 4-stage cp.async, ONE sync per k-tile.
// 8 warps (4m x 2n), warp tile 32x64, all fragments via ldmatrix.x4.
// ============================================================================
#define G_LD   40                          // halves per row (32+8 pad)
#define G_STG  (128 * G_LD)                // halves per operand per stage
#define G_NSTG 4
#define G_SMEM (G_NSTG * 2 * G_STG * 2)    // 81920 B

struct GemmAcc { float a[2][8][4]; };

__device__ __forceinline__ void gemm_core(
    const __half* __restrict__ A, const __half* __restrict__ Bt,
    int row0, int col0, GemmAcc& acc, __half* gsm)
{
    const int tid = threadIdx.x;
    const int lane = tid & 31, wid = tid >> 5;
    const int wm = wid & 3, wn = wid >> 2;

    uint32_t sA = (uint32_t)__cvta_generic_to_shared(gsm);
    uint32_t sB = sA + G_NSTG * G_STG * 2;

    // ldmatrix per-lane addressing
    const int a_row = (lane & 7) + ((lane >> 3) & 1) * 8;   // m within 16
    const int a_kof = ((lane >> 4) & 1) * 8;
    const int b_row = (lane & 7) + ((lane >> 4) & 1) * 8;   // n within 16
    const int b_kof = ((lane >> 3) & 1) * 8;

    #pragma unroll
    for (int mt = 0; mt < 2; mt++)
        #pragma unroll
        for (int nt = 0; nt < 8; nt++)
            #pragma unroll
            for (int r = 0; r < 4; r++) acc.a[mt][nt][r] = 0.f;

    const int NT = DM / 32;   // 32
    auto issue = [&](int t) {
        if (t < NT) {
            int buf = t % G_NSTG, k0 = t * 32;
            #pragma unroll
            for (int i = 0; i < 2; i++) {
                int idx = tid + i * 256;
                int r = idx >> 2, c = idx & 3;
                uint32_t off = (uint32_t)(buf * G_STG + r * G_LD + c * 8) * 2;
                cp16s(sA + off, A  + (size_t)(row0 + r) * DM + k0 + c * 8);
                cp16s(sB + off, Bt + (size_t)(col0 + r) * DM + k0 + c * 8);
            }
        }
        cp_commit();
    };

    issue(0); issue(1); issue(2);

    for (int it = 0; it < NT; ++it) {
        asm volatile("cp.async.wait_group 2;" ::: "memory");
        __syncthreads();

        uint32_t ab = sA + (uint32_t)((it % G_NSTG) * G_STG) * 2;
        uint32_t bb = sB + (uint32_t)((it % G_NSTG) * G_STG) * 2;

        #pragma unroll
        for (int ks = 0; ks < 2; ks++) {
            uint32_t a[2][4];
            #pragma unroll
            for (int mt = 0; mt < 2; mt++)
                ldm4(a[mt], ab + (uint32_t)((wm * 32 + mt * 16 + a_row) * G_LD
                                            + ks * 16 + a_kof) * 2);
            #pragma unroll
            for (int ntp = 0; ntp < 4; ntp++) {
                uint32_t bf[4];
                ldm4(bf, bb + (uint32_t)((wn * 64 + ntp * 16 + b_row) * G_LD
                                         + ks * 16 + b_kof) * 2);
                mma_f16(acc.a[0][2 * ntp],     a[0], bf[0], bf[1]);
                mma_f16(acc.a[0][2 * ntp + 1], a[0], bf[2], bf[3]);
                mma_f16(acc.a[1][2 * ntp],     a[1], bf[0], bf[1]);
                mma_f16(acc.a[1][2 * ntp + 1], a[1], bf[2], bf[3]);
            }
        }
        issue(it + 3);
    }
}

// Fused QKV: grid (24, 32). mat = bx>>3 selects weight + destination.
__global__ __launch_bounds__(256, 2) void gemm_qkv(
    const __half* __restrict__ A, const __half* __restrict__ W,
    __half* __restrict__ Qh, __half* __restrict__ Kh, __half* __restrict__ Vh)
{
    extern __shared__ __align__(16) __half gsm[];
    const int mat = blockIdx.x >> 3;
    const int col0 = (blockIdx.x & 7) * 128;
    const int row0 = blockIdx.y * 128;
    const __half* Bt = W + (size_t)mat * DM * DM;
    __half* C = (mat == 0) ? Qh : (mat == 1) ? Kh : Vh;
    const float sc = (mat == 0) ? QSCALE : 1.f;

    GemmAcc acc;
    gemm_core(A, Bt, row0, col0, acc, gsm);

    const int lane = threadIdx.x & 31, wid = threadIdx.x >> 5;
    const int lr = lane >> 2, lc = lane & 3;
    const int wm = wid & 3, wn = wid >> 2;
    #pragma unroll
    for (int mt = 0; mt < 2; mt++) {
        int r = row0 + wm * 32 + mt * 16 + lr;
        #pragma unroll
        for (int nt = 0; nt < 8; nt++) {
            int c = col0 + wn * 64 + nt * 8 + 2 * lc;
            *(__half2*)&C[(size_t)r * DM + c] =
                __floats2half2_rn(acc.a[mt][nt][0] * sc, acc.a[mt][nt][1] * sc);
            *(__half2*)&C[(size_t)(r + 8) * DM + c] =
                __floats2half2_rn(acc.a[mt][nt][2] * sc, acc.a[mt][nt][3] * sc);
        }
    }
}

// Out projection: fp32 output + bias
__global__ __launch_bounds__(256, 2) void gemm_out(
    const __half* __restrict__ A, const __half* __restrict__ Bt,
    const float* __restrict__ bias, float* __restrict__ Cf)
{
    extern __shared__ __align__(16) __half gsm[];
    const int col0 = blockIdx.x * 128, row0 = blockIdx.y * 128;

    GemmAcc acc;
    gemm_core(A, Bt, row0, col0, acc, gsm);

    const int lane = threadIdx.x & 31, wid = threadIdx.x >> 5;
    const int lr = lane >> 2, lc = lane & 3;
    const int wm = wid & 3, wn = wid >> 2;
    #pragma unroll
    for (int mt = 0; mt < 2; mt++) {
        int r = row0 + wm * 32 + mt * 16 + lr;
        #pragma unroll
        for (int nt = 0; nt < 8; nt++) {
            int c = col0 + wn * 64 + nt * 8 + 2 * lc;
            float bx = bias[c], by = bias[c + 1];
            *(float2*)&Cf[(size_t)r * DM + c] =
                make_float2(acc.a[mt][nt][0] + bx, acc.a[mt][nt][1] + by);
            *(float2*)&Cf[(size_t)(r + 8) * DM + c] =
                make_float2(acc.a[mt][nt][2] + bx, acc.a[mt][nt][3] + by);
        }
    }
}

// ============================================================================
// fp16 flash attention (causal, exp2 domain). 128 q/CTA, 64 kv/tile.
// 3-buffer cp.async pipeline, ONE sync per tile. P in registers, Q/K via ldmatrix.
// ============================================================================
#define F_LD   72
#define F_QP   (128 * F_LD)
#define F_KV   (64 * F_LD)
#define F_SMEM ((F_QP + 3 * F_KV + 3 * F_KV) * 2)   // 73728 B

__global__ __launch_bounds__(256, 2) void flash_h(
    const __half* __restrict__ Q, const __half* __restrict__ K,
    const __half* __restrict__ V, __half* __restrict__ O)
{
    extern __shared__ __align__(16) __half fsm[];
    const int tid = threadIdx.x;
    const int lane = tid & 31, wid = tid >> 5;
    const int lr = lane >> 2, lc = lane & 3;
    const int q0 = (gridDim.x - 1 - blockIdx.x) * 128;   // heavy tiles first
    const int h = blockIdx.y, b = blockIdx.z;

    const __half* Qg = Q + (size_t)(b * CTX) * DM + h * HD;
    const __half* Kg = K + (size_t)(b * CTX) * DM + h * HD;
    const __half* Vg = V + (size_t)(b * CTX) * DM + h * HD;

    uint32_t sQ = (uint32_t)__cvta_generic_to_shared(fsm);
    uint32_t sK = sQ + F_QP * 2;
    uint32_t sV = sK + 3 * F_KV * 2;

    const int a_row = (lane & 7) + ((lane >> 3) & 1) * 8;
    const int a_kof = ((lane >> 4) & 1) * 8;
    const int b_row = (lane & 7) + ((lane >> 4) & 1) * 8;
    const int b_kof = ((lane >> 3) & 1) * 8;

    const int nkv = q0 / 64 + 2;

    auto issueKV = [&](int t) {
        if (t < nkv) {
            int kb = t * 64, buf = t % 3;
            #pragma unroll
            for (int i = 0; i < 4; i++) {
                int idx = tid + i * 256;
                int sel = idx >> 9;
                int kk = (idx >> 3) & 63, c = idx & 7;
                const __half* src = (sel ? Vg : Kg) + (size_t)(kb + kk) * DM + c * 8;
                uint32_t dst = (sel ? sV : sK) +
                               (uint32_t)(buf * F_KV + kk * F_LD + c * 8) * 2;
                cp16s(dst, src);
            }
        }
        cp_commit();
    };

    // prologue: Q tile joins tile-0's commit group
    #pragma unroll
    for (int i = 0; i < 4; i++) {
        int idx = tid + i * 256;
        int q = idx >> 3, c = idx & 7;
        cp16s(sQ + (uint32_t)(q * F_LD + c * 8) * 2, Qg + (size_t)(q0 + q) * DM + c * 8);
    }
    issueKV(0);
    issueKV(1);

    float m0 = -INFINITY, m1 = -INFINITY, l0 = 0.f, l1 = 0.f;
    float o[8][4];
    #pragma unroll
    for (int dt = 0; dt < 8; dt++)
        #pragma unroll
        for (int r = 0; r < 4; r++) o[dt][r] = 0.f;

    const int qw = wid * 16;
    const int vrow = lane & 15;
    const int vblk = lane >> 4;

    for (int t = 0; t < nkv; ++t) {
        asm volatile("cp.async.wait_group 1;" ::: "memory");
        __syncthreads();

        uint32_t kbuf = sK + (uint32_t)((t % 3) * F_KV) * 2;
        uint32_t vbuf = sV + (uint32_t)((t % 3) * F_KV) * 2;

        // ---- S = Q @ K^T (warp: 16 x 64), log2 domain ----
        float s[8][4];
        #pragma unroll
        for (int nt = 0; nt < 8; nt++)
            #pragma unroll
            for (int r = 0; r < 4; r++) s[nt][r] = 0.f;

        #pragma unroll
        for (int ks = 0; ks < 4; ks++) {
            uint32_t a[4];
            ldm4(a, sQ + (uint32_t)((qw + a_row) * F_LD + ks * 16 + a_kof) * 2);
            #pragma unroll
            for (int ntp = 0; ntp < 4; ntp++) {
                uint32_t bf[4];
                ldm4(bf, kbuf + (uint32_t)((ntp * 16 + b_row) * F_LD
                                           + ks * 16 + b_kof) * 2);
                mma_f16(s[2 * ntp],     a, bf[0], bf[1]);
                mma_f16(s[2 * ntp + 1], a, bf[2], bf[3]);
            }
        }

        const int kb = t * 64;
        const int r0 = q0 + qw + lr, r1 = r0 + 8;

        if (kb + 63 > q0) {
            #pragma unroll
            for (int nt = 0; nt < 8; nt++) {
                #pragma unroll
                for (int j = 0; j < 2; j++) {
                    int key = kb + nt * 8 + 2 * lc + j;
                    if (key > r0) s[nt][j]     = -1e30f;
                    if (key > r1) s[nt][2 + j] = -1e30f;
                }
            }
        }

        // ---- online softmax (exp2 domain) ----
        float rm0 = -1e30f, rm1 = -1e30f;
        #pragma unroll
        for (int nt = 0; nt < 8; nt++) {
            rm0 = fmaxf(rm0, fmaxf(s[nt][0], s[nt][1]));
            rm1 = fmaxf(rm1, fmaxf(s[nt][2], s[nt][3]));
        }
        rm0 = fmaxf(rm0, __shfl_xor_sync(0xffffffffu, rm0, 1));
        rm0 = fmaxf(rm0, __shfl_xor_sync(0xffffffffu, rm0, 2));
        rm1 = fmaxf(rm1, __shfl_xor_sync(0xffffffffu, rm1, 1));
        rm1 = fmaxf(rm1, __shfl_xor_sync(0xffffffffu, rm1, 2));

        float mn0 = fmaxf(m0, rm0), mn1 = fmaxf(m1, rm1);
        float c0 = ex2(m0 - mn0), c1 = ex2(m1 - mn1);
        float rs0 = 0.f, rs1 = 0.f;
        #pragma unroll
        for (int nt = 0; nt < 8; nt++) {
            s[nt][0] = ex2(s[nt][0] - mn0);
            s[nt][1] = ex2(s[nt][1] - mn0);
            s[nt][2] = ex2(s[nt][2] - mn1);
            s[nt][3] = ex2(s[nt][3] - mn1);
            rs0 += s[nt][0] + s[nt][1];
            rs1 += s[nt][2] + s[nt][3];
        }
        rs0 += __shfl_xor_sync(0xffffffffu, rs0, 1);
        rs0 += __shfl_xor_sync(0xffffffffu, rs0, 2);
        rs1 += __shfl_xor_sync(0xffffffffu, rs1, 1);
        rs1 += __shfl_xor_sync(0xffffffffu, rs1, 2);

        l0 = l0 * c0 + rs0; m0 = mn0;
        l1 = l1 * c1 + rs1; m1 = mn1;
        #pragma unroll
        for (int dt = 0; dt < 8; dt++) {
            o[dt][0] *= c0; o[dt][1] *= c0;
            o[dt][2] *= c1; o[dt][3] *= c1;
        }

        // ---- O += P @ V : P packed from registers (C-frag == A-frag layout) ----
        #pragma unroll
        for (int ks = 0; ks < 4; ks++) {
            uint32_t a[4];
            a[0] = packh2(s[2 * ks][0],     s[2 * ks][1]);
            a[1] = packh2(s[2 * ks][2],     s[2 * ks][3]);
            a[2] = packh2(s[2 * ks + 1][0], s[2 * ks + 1][1]);
            a[3] = packh2(s[2 * ks + 1][2], s[2 * ks + 1][3]);
            #pragma unroll
            for (int ntp = 0; ntp < 4; ntp++) {
                uint32_t b0, b1, b2, b3;
                uint32_t addr = vbuf +
                    (uint32_t)((ks * 16 + vrow) * F_LD + (2 * ntp + vblk) * 8) * 2;
                ldm4t(b0, b1, b2, b3, addr);
                mma_f16(o[2 * ntp],     a, b0, b1);
                mma_f16(o[2 * ntp + 1], a, b2, b3);
            }
        }
        issueKV(t + 2);
    }

    // ---- normalize + write ctx (fp16) ----
    float i0 = 1.f / l0, i1 = 1.f / l1;
    const int r0 = q0 + qw + lr;
    __half* Og = O + (size_t)(b * CTX) * DM + h * HD;
    #pragma unroll
    for (int dt = 0; dt < 8; dt++) {
        int c = dt * 8 + 2 * lc;
        *(__half2*)&Og[(size_t)r0 * DM + c] =
            __floats2half2_rn(o[dt][0] * i0, o[dt][1] * i0);
        *(__half2*)&Og[(size_t)(r0 + 8) * DM + c] =
            __floats2half2_rn(o[dt][2] * i1, o[dt][3] * i1);
    }
}

// ---- tiny kernel to publish weight source pointers (graph-capturable) ----
__global__ void set_wsrc(const float* wq, const float* wk, const float* wv, const float* wo) {
    g_wsrc[0] = wq; g_wsrc[1] = wk; g_wsrc[2] = wv; g_wsrc[3] = wo;
}

// ============================================================================
// launch
// ============================================================================
extern "C" void kernel_launch(void* const* d_in, const int* in_sizes, int n_in,
                              void* d_out, int out_size)
{
    const float* x  = (const float*)d_in[0];
    const float* Wq = (const float*)d_in[1];
    const float* Wk = (const float*)d_in[2];
    const float* Wv = (const float*)d_in[3];
    const float* Wo = (const float*)d_in[4];
    const float* bo = (const float*)d_in[5];
    float* out = (float*)d_out;

    __half *Xh, *Wh, *Qh, *Kh, *Vh, *Ch;
    cudaGetSymbolAddress((void**)&Xh, g_Xh);
    cudaGetSymbolAddress((void**)&Wh, g_Wh);
    cudaGetSymbolAddress((void**)&Qh, g_Qh);
    cudaGetSymbolAddress((void**)&Kh, g_Kh);
    cudaGetSymbolAddress((void**)&Vh, g_Vh);
    cudaGetSymbolAddress((void**)&Ch, g_Ch);
    const float** wsrc;
    cudaGetSymbolAddress((void**)&wsrc, g_wsrc);

    cudaFuncSetAttribute(gemm_qkv, cudaFuncAttributeMaxDynamicSharedMemorySize, G_SMEM);
    cudaFuncSetAttribute(gemm_out, cudaFuncAttributeMaxDynamicSharedMemorySize, G_SMEM);
    cudaFuncSetAttribute(flash_h, cudaFuncAttributeMaxDynamicSharedMemorySize, F_SMEM);

    const int NX4 = BT * DM / 4;
    conv_x<<<NX4 / 256, 256>>>((const float4*)x, (__half2*)Xh, NX4);

    set_wsrc<<<1, 1>>>(Wq, Wk, Wv, Wo);
    dim3 tgrid(DM / 32, DM / 32, 4), tblk(32, 8);
    conv_wT<<<tgrid, tblk>>>(wsrc, Wh);

    dim3 qgrid(24, BT / 128);          // fused QKV
    gemm_qkv<<<qgrid, 256, G_SMEM>>>(Xh, Wh, Qh, Kh, Vh);

    dim3 fgrid(CTX / 128, NH, BATCH);  // (16, 16, 2)
    flash_h<<<fgrid, 256, F_SMEM>>>(Qh, Kh, Vh, Ch);

    dim3 ogrid(DM / 128, BT / 128);
    gemm_out<<<ogrid, 256, G_SMEM>>>(Ch, Wh + 3 * (size_t)DM * DM, bo, out);
}

// round 8
// speedup vs baseline: 2.5176x; 1.1485x over previous
#include <cuda_runtime.h>
#include <cuda_fp16.h>
#include <math.h>
#include <stdint.h>

#define BATCH 2
#define CTX   2048
#define DM    1024
#define NH    16
#define HD    64
#define BT    (BATCH*CTX)   // 4096

// ---------------- scratch (device globals; no allocation allowed) ----------
__device__ __half g_Xh[BT * DM];
__device__ __half g_Wh[4 * DM * DM];   // transposed weights [N][K], fp16
__device__ __half g_Qh[BT * DM];
__device__ __half g_Kh[BT * DM];
__device__ __half g_Vh[BT * DM];
__device__ __half g_Ch[BT * DM];

// Q projections pre-scaled by 1/sqrt(64) * log2(e): flash works in exp2 domain
#define QSCALE 0.18033688011112042f

// ---------------- helpers ---------------------------------------------------
__device__ __forceinline__ void mma_f16(float* d, const uint32_t* a, uint32_t b0, uint32_t b1) {
    asm volatile(
        "mma.sync.aligned.m16n8k16.row.col.f32.f16.f16.f32 "
        "{%0,%1,%2,%3}, {%4,%5,%6,%7}, {%8,%9}, {%0,%1,%2,%3};"
        : "+f"(d[0]), "+f"(d[1]), "+f"(d[2]), "+f"(d[3])
        : "r"(a[0]), "r"(a[1]), "r"(a[2]), "r"(a[3]), "r"(b0), "r"(b1));
}

__device__ __forceinline__ void ldm4(uint32_t* r, uint32_t addr) {
    asm volatile("ldmatrix.sync.aligned.m8n8.x4.shared.b16 {%0,%1,%2,%3}, [%4];"
                 : "=r"(r[0]), "=r"(r[1]), "=r"(r[2]), "=r"(r[3]) : "r"(addr));
}
__device__ __forceinline__ void ldm4t(uint32_t& r0, uint32_t& r1, uint32_t& r2, uint32_t& r3,
                                      uint32_t addr) {
    asm volatile("ldmatrix.sync.aligned.m8n8.x4.trans.shared.b16 {%0,%1,%2,%3}, [%4];"
                 : "=r"(r0), "=r"(r1), "=r"(r2), "=r"(r3) : "r"(addr));
}

__device__ __forceinline__ void cp16s(uint32_t dst, const void* g) {
    asm volatile("cp.async.ca.shared.global [%0], [%1], 16;" :: "r"(dst), "l"(g));
}
__device__ __forceinline__ void cp_commit() {
    asm volatile("cp.async.commit_group;" ::: "memory");
}
__device__ __forceinline__ uint32_t packh2(float x, float y) {
    __half2 h = __floats2half2_rn(x, y);
    return *(uint32_t*)&h;
}
__device__ __forceinline__ float ex2(float x) {
    float y; asm("ex2.approx.f32 %0, %1;" : "=f"(y) : "f"(x)); return y;
}

// ---------------- converters -------------------------------------------------
__global__ __launch_bounds__(256) void conv_x(const float4* __restrict__ in,
                                              __half2* __restrict__ out, int n4) {
    int i = blockIdx.x * 256 + threadIdx.x;
    if (i < n4) {
        float4 v = in[i];
        out[2 * i]     = __floats2half2_rn(v.x, v.y);
        out[2 * i + 1] = __floats2half2_rn(v.z, v.w);
    }
}

__device__ const float* g_wsrc[4];
// W[k][n] fp32 -> out[n][k] fp16  (4 matrices via blockIdx.z)
__global__ void conv_wT(const float* const* __restrict__ srcs, __half* __restrict__ out) {
    __shared__ float tle[32][33];
    const float* in = srcs[blockIdx.z];
    __half* o = out + (size_t)blockIdx.z * DM * DM;
    int bx = blockIdx.x * 32, by = blockIdx.y * 32;
    int tx = threadIdx.x, ty = threadIdx.y;
    #pragma unroll
    for (int i = 0; i < 4; i++)
        tle[ty + 8 * i][tx] = in[(size_t)(by + ty + 8 * i) * DM + bx + tx];
    __syncthreads();
    #pragma unroll
    for (int i = 0; i < 4; i++)
        o[(size_t)(bx + ty + 8 * i) * DM + by + tx] = __float2half_rn(tle[tx][ty + 8 * i]);
}

// ============================================================================
// fp16 GEMM core. BM=BN=128, BK=32, 4-stage cp.async, ONE sync per k-tile.
// 4 warps (2m x 2n), warp tile 64x64, fragments via ldmatrix.x4.
// ============================================================================
#define G_LD   40                          // halves per row (32+8 pad)
#define G_STG  (128 * G_LD)                // halves per operand per stage
#define G_NSTG 4
#define G_SMEM (G_NSTG * 2 * G_STG * 2)    // 81920 B

struct GemmAcc { float a[4][8][4]; };

__device__ __forceinline__ void gemm_core(
    const __half* __restrict__ A, const __half* __restrict__ Bt,
    int row0, int col0, GemmAcc& acc, __half* gsm)
{
    const int tid = threadIdx.x;
    const int lane = tid & 31, wid = tid >> 5;
    const int wm = wid & 1, wn = wid >> 1;

    uint32_t sA = (uint32_t)__cvta_generic_to_shared(gsm);
    uint32_t sB = sA + G_NSTG * G_STG * 2;

    const int a_row = (lane & 7) + ((lane >> 3) & 1) * 8;
    const int a_kof = ((lane >> 4) & 1) * 8;
    const int b_row = (lane & 7) + ((lane >> 4) & 1) * 8;
    const int b_kof = ((lane >> 3) & 1) * 8;

    #pragma unroll
    for (int mt = 0; mt < 4; mt++)
        #pragma unroll
        for (int nt = 0; nt < 8; nt++)
            #pragma unroll
            for (int r = 0; r < 4; r++) acc.a[mt][nt][r] = 0.f;

    const int NT = DM / 32;   // 32
    auto issue = [&](int t) {
        if (t < NT) {
            int buf = t % G_NSTG, k0 = t * 32;
            #pragma unroll
            for (int i = 0; i < 4; i++) {
                int idx = tid + i * 128;          // 0..511
                int r = idx >> 2, c = idx & 3;
                uint32_t off = (uint32_t)(buf * G_STG + r * G_LD + c * 8) * 2;
                cp16s(sA + off, A  + (size_t)(row0 + r) * DM + k0 + c * 8);
                cp16s(sB + off, Bt + (size_t)(col0 + r) * DM + k0 + c * 8);
            }
        }
        cp_commit();
    };

    issue(0); issue(1); issue(2);

    for (int it = 0; it < NT; ++it) {
        asm volatile("cp.async.wait_group 2;" ::: "memory");
        __syncthreads();

        uint32_t ab = sA + (uint32_t)((it % G_NSTG) * G_STG) * 2;
        uint32_t bb = sB + (uint32_t)((it % G_NSTG) * G_STG) * 2;

        #pragma unroll
        for (int ks = 0; ks < 2; ks++) {
            uint32_t a[4][4];
            #pragma unroll
            for (int mt = 0; mt < 4; mt++)
                ldm4(a[mt], ab + (uint32_t)((wm * 64 + mt * 16 + a_row) * G_LD
                                            + ks * 16 + a_kof) * 2);
            #pragma unroll
            for (int ntp = 0; ntp < 4; ntp++) {
                uint32_t bf[4];
                ldm4(bf, bb + (uint32_t)((wn * 64 + ntp * 16 + b_row) * G_LD
                                         + ks * 16 + b_kof) * 2);
                #pragma unroll
                for (int mt = 0; mt < 4; mt++) {
                    mma_f16(acc.a[mt][2 * ntp],     a[mt], bf[0], bf[1]);
                    mma_f16(acc.a[mt][2 * ntp + 1], a[mt], bf[2], bf[3]);
                }
            }
        }
        issue(it + 3);
    }
}

// Fused QKV: grid (24, 32). mat = bx>>3 selects weight + destination.
__global__ __launch_bounds__(128, 2) void gemm_qkv(
    const __half* __restrict__ A, const __half* __restrict__ W,
    __half* __restrict__ Qh, __half* __restrict__ Kh, __half* __restrict__ Vh)
{
    extern __shared__ __align__(16) __half gsm[];
    const int mat = blockIdx.x >> 3;
    const int col0 = (blockIdx.x & 7) * 128;
    const int row0 = blockIdx.y * 128;
    const __half* Bt = W + (size_t)mat * DM * DM;
    __half* C = (mat == 0) ? Qh : (mat == 1) ? Kh : Vh;
    const float sc = (mat == 0) ? QSCALE : 1.f;

    GemmAcc acc;
    gemm_core(A, Bt, row0, col0, acc, gsm);

    const int lane = threadIdx.x & 31, wid = threadIdx.x >> 5;
    const int lr = lane >> 2, lc = lane & 3;
    const int wm = wid & 1, wn = wid >> 1;
    #pragma unroll
    for (int mt = 0; mt < 4; mt++) {
        int r = row0 + wm * 64 + mt * 16 + lr;
        #pragma unroll
        for (int nt = 0; nt < 8; nt++) {
            int c = col0 + wn * 64 + nt * 8 + 2 * lc;
            *(__half2*)&C[(size_t)r * DM + c] =
                __floats2half2_rn(acc.a[mt][nt][0] * sc, acc.a[mt][nt][1] * sc);
            *(__half2*)&C[(size_t)(r + 8) * DM + c] =
                __floats2half2_rn(acc.a[mt][nt][2] * sc, acc.a[mt][nt][3] * sc);
        }
    }
}

// Out projection: fp32 output + bias
__global__ __launch_bounds__(128, 2) void gemm_out(
    const __half* __restrict__ A, const __half* __restrict__ Bt,
    const float* __restrict__ bias, float* __restrict__ Cf)
{
    extern __shared__ __align__(16) __half gsm[];
    const int col0 = blockIdx.x * 128, row0 = blockIdx.y * 128;

    GemmAcc acc;
    gemm_core(A, Bt, row0, col0, acc, gsm);

    const int lane = threadIdx.x & 31, wid = threadIdx.x >> 5;
    const int lr = lane >> 2, lc = lane & 3;
    const int wm = wid & 1, wn = wid >> 1;
    #pragma unroll
    for (int mt = 0; mt < 4; mt++) {
        int r = row0 + wm * 64 + mt * 16 + lr;
        #pragma unroll
        for (int nt = 0; nt < 8; nt++) {
            int c = col0 + wn * 64 + nt * 8 + 2 * lc;
            float bx = bias[c], by = bias[c + 1];
            *(float2*)&Cf[(size_t)r * DM + c] =
                make_float2(acc.a[mt][nt][0] + bx, acc.a[mt][nt][1] + by);
            *(float2*)&Cf[(size_t)(r + 8) * DM + c] =
                make_float2(acc.a[mt][nt][2] + bx, acc.a[mt][nt][3] + by);
        }
    }
}

// ============================================================================
// fp16 flash attention (causal, exp2 domain). 128 q/CTA, 64 kv/tile.
// 4 warps, warp owns 32 q-rows (mt=2). 3-buffer cp.async, ONE sync per tile.
// ============================================================================
#define F_LD   72
#define F_QP   (128 * F_LD)
#define F_KV   (64 * F_LD)
#define F_SMEM ((F_QP + 3 * F_KV + 3 * F_KV) * 2)   // 73728 B

__global__ __launch_bounds__(128, 2) void flash_h(
    const __half* __restrict__ Q, const __half* __restrict__ K,
    const __half* __restrict__ V, __half* __restrict__ O)
{
    extern __shared__ __align__(16) __half fsm[];
    const int tid = threadIdx.x;
    const int lane = tid & 31, wid = tid >> 5;
    const int lr = lane >> 2, lc = lane & 3;
    const int q0 = (gridDim.x - 1 - blockIdx.x) * 128;   // heavy tiles first
    const int h = blockIdx.y, b = blockIdx.z;

    const __half* Qg = Q + (size_t)(b * CTX) * DM + h * HD;
    const __half* Kg = K + (size_t)(b * CTX) * DM + h * HD;
    const __half* Vg = V + (size_t)(b * CTX) * DM + h * HD;

    uint32_t sQ = (uint32_t)__cvta_generic_to_shared(fsm);
    uint32_t sK = sQ + F_QP * 2;
    uint32_t sV = sK + 3 * F_KV * 2;

    const int a_row = (lane & 7) + ((lane >> 3) & 1) * 8;
    const int a_kof = ((lane >> 4) & 1) * 8;
    const int b_row = (lane & 7) + ((lane >> 4) & 1) * 8;
    const int b_kof = ((lane >> 3) & 1) * 8;

    const int nkv = q0 / 64 + 2;

    auto issueKV = [&](int t) {
        if (t < nkv) {
            int kb = t * 64, buf = t % 3;
            #pragma unroll
            for (int i = 0; i < 8; i++) {
                int idx = tid + i * 128;
                int sel = idx >> 9;
                int kk = (idx >> 3) & 63, c = idx & 7;
                const __half* src = (sel ? Vg : Kg) + (size_t)(kb + kk) * DM + c * 8;
                uint32_t dst = (sel ? sV : sK) +
                               (uint32_t)(buf * F_KV + kk * F_LD + c * 8) * 2;
                cp16s(dst, src);
            }
        }
        cp_commit();
    };

    // prologue: Q tile joins tile-0's commit group
    #pragma unroll
    for (int i = 0; i < 8; i++) {
        int idx = tid + i * 128;
        int q = idx >> 3, c = idx & 7;
        cp16s(sQ + (uint32_t)(q * F_LD + c * 8) * 2, Qg + (size_t)(q0 + q) * DM + c * 8);
    }
    issueKV(0);
    issueKV(1);

    float m0[2], m1[2], l0[2], l1[2];
    float o[2][8][4];
    #pragma unroll
    for (int mt = 0; mt < 2; mt++) {
        m0[mt] = -INFINITY; m1[mt] = -INFINITY; l0[mt] = 0.f; l1[mt] = 0.f;
        #pragma unroll
        for (int dt = 0; dt < 8; dt++)
            #pragma unroll
            for (int r = 0; r < 4; r++) o[mt][dt][r] = 0.f;
    }

    const int qw = wid * 32;
    const int vrow = lane & 15;
    const int vblk = lane >> 4;

    for (int t = 0; t < nkv; ++t) {
        asm volatile("cp.async.wait_group 1;" ::: "memory");
        __syncthreads();

        uint32_t kbuf = sK + (uint32_t)((t % 3) * F_KV) * 2;
        uint32_t vbuf = sV + (uint32_t)((t % 3) * F_KV) * 2;

        // ---- S = Q @ K^T (warp: 32 x 64), log2 domain ----
        float s[2][8][4];
        #pragma unroll
        for (int mt = 0; mt < 2; mt++)
            #pragma unroll
            for (int nt = 0; nt < 8; nt++)
                #pragma unroll
                for (int r = 0; r < 4; r++) s[mt][nt][r] = 0.f;

        #pragma unroll
        for (int ks = 0; ks < 4; ks++) {
            uint32_t a[2][4];
            #pragma unroll
            for (int mt = 0; mt < 2; mt++)
                ldm4(a[mt], sQ + (uint32_t)((qw + mt * 16 + a_row) * F_LD
                                            + ks * 16 + a_kof) * 2);
            #pragma unroll
            for (int ntp = 0; ntp < 4; ntp++) {
                uint32_t bf[4];
                ldm4(bf, kbuf + (uint32_t)((ntp * 16 + b_row) * F_LD
                                           + ks * 16 + b_kof) * 2);
                #pragma unroll
                for (int mt = 0; mt < 2; mt++) {
                    mma_f16(s[mt][2 * ntp],     a[mt], bf[0], bf[1]);
                    mma_f16(s[mt][2 * ntp + 1], a[mt], bf[2], bf[3]);
                }
            }
        }

        const int kb = t * 64;

        if (kb + 63 > q0) {
            #pragma unroll
            for (int mt = 0; mt < 2; mt++) {
                int r0 = q0 + qw + mt * 16 + lr, r1 = r0 + 8;
                #pragma unroll
                for (int nt = 0; nt < 8; nt++) {
                    #pragma unroll
                    for (int j = 0; j < 2; j++) {
                        int key = kb + nt * 8 + 2 * lc + j;
                        if (key > r0) s[mt][nt][j]     = -1e30f;
                        if (key > r1) s[mt][nt][2 + j] = -1e30f;
                    }
                }
            }
        }

        // ---- online softmax (exp2 domain) ----
        #pragma unroll
        for (int mt = 0; mt < 2; mt++) {
            float rm0 = -1e30f, rm1 = -1e30f;
            #pragma unroll
            for (int nt = 0; nt < 8; nt++) {
                rm0 = fmaxf(rm0, fmaxf(s[mt][nt][0], s[mt][nt][1]));
                rm1 = fmaxf(rm1, fmaxf(s[mt][nt][2], s[mt][nt][3]));
            }
            rm0 = fmaxf(rm0, __shfl_xor_sync(0xffffffffu, rm0, 1));
            rm0 = fmaxf(rm0, __shfl_xor_sync(0xffffffffu, rm0, 2));
            rm1 = fmaxf(rm1, __shfl_xor_sync(0xffffffffu, rm1, 1));
            rm1 = fmaxf(rm1, __shfl_xor_sync(0xffffffffu, rm1, 2));

            float mn0 = fmaxf(m0[mt], rm0), mn1 = fmaxf(m1[mt], rm1);
            float c0 = ex2(m0[mt] - mn0), c1 = ex2(m1[mt] - mn1);
            float rs0 = 0.f, rs1 = 0.f;
            #pragma unroll
            for (int nt = 0; nt < 8; nt++) {
                s[mt][nt][0] = ex2(s[mt][nt][0] - mn0);
                s[mt][nt][1] = ex2(s[mt][nt][1] - mn0);
                s[mt][nt][2] = ex2(s[mt][nt][2] - mn1);
                s[mt][nt][3] = ex2(s[mt][nt][3] - mn1);
                rs0 += s[mt][nt][0] + s[mt][nt][1];
                rs1 += s[mt][nt][2] + s[mt][nt][3];
            }
            rs0 += __shfl_xor_sync(0xffffffffu, rs0, 1);
            rs0 += __shfl_xor_sync(0xffffffffu, rs0, 2);
            rs1 += __shfl_xor_sync(0xffffffffu, rs1, 1);
            rs1 += __shfl_xor_sync(0xffffffffu, rs1, 2);

            l0[mt] = l0[mt] * c0 + rs0; m0[mt] = mn0;
            l1[mt] = l1[mt] * c1 + rs1; m1[mt] = mn1;
            #pragma unroll
            for (int dt = 0; dt < 8; dt++) {
                o[mt][dt][0] *= c0; o[mt][dt][1] *= c0;
                o[mt][dt][2] *= c1; o[mt][dt][3] *= c1;
            }
        }

        // ---- O += P @ V : P packed from registers ----
        #pragma unroll
        for (int ks = 0; ks < 4; ks++) {
            uint32_t a[2][4];
            #pragma unroll
            for (int mt = 0; mt < 2; mt++) {
                a[mt][0] = packh2(s[mt][2 * ks][0],     s[mt][2 * ks][1]);
                a[mt][1] = packh2(s[mt][2 * ks][2],     s[mt][2 * ks][3]);
                a[mt][2] = packh2(s[mt][2 * ks + 1][0], s[mt][2 * ks + 1][1]);
                a[mt][3] = packh2(s[mt][2 * ks + 1][2], s[mt][2 * ks + 1][3]);
            }
            #pragma unroll
            for (int ntp = 0; ntp < 4; ntp++) {
                uint32_t b0, b1, b2, b3;
                uint32_t addr = vbuf +
                    (uint32_t)((ks * 16 + vrow) * F_LD + (2 * ntp + vblk) * 8) * 2;
                ldm4t(b0, b1, b2, b3, addr);
                #pragma unroll
                for (int mt = 0; mt < 2; mt++) {
                    mma_f16(o[mt][2 * ntp],     a[mt], b0, b1);
                    mma_f16(o[mt][2 * ntp + 1], a[mt], b2, b3);
                }
            }
        }
        issueKV(t + 2);
    }

    // ---- normalize + write ctx (fp16) ----
    __half* Og = O + (size_t)(b * CTX) * DM + h * HD;
    #pragma unroll
    for (int mt = 0; mt < 2; mt++) {
        float i0 = 1.f / l0[mt], i1 = 1.f / l1[mt];
        int r0 = q0 + qw + mt * 16 + lr;
        #pragma unroll
        for (int dt = 0; dt < 8; dt++) {
            int c = dt * 8 + 2 * lc;
            *(__half2*)&Og[(size_t)r0 * DM + c] =
                __floats2half2_rn(o[mt][dt][0] * i0, o[mt][dt][1] * i0);
            *(__half2*)&Og[(size_t)(r0 + 8) * DM + c] =
                __floats2half2_rn(o[mt][dt][2] * i1, o[mt][dt][3] * i1);
        }
    }
}

// ---- tiny kernel to publish weight source pointers (graph-capturable) ----
__global__ void set_wsrc(const float* wq, const float* wk, const float* wv, const float* wo) {
    g_wsrc[0] = wq; g_wsrc[1] = wk; g_wsrc[2] = wv; g_wsrc[3] = wo;
}

// ============================================================================
// launch
// ============================================================================
extern "C" void kernel_launch(void* const* d_in, const int* in_sizes, int n_in,
                              void* d_out, int out_size)
{
    const float* x  = (const float*)d_in[0];
    const float* Wq = (const float*)d_in[1];
    const float* Wk = (const float*)d_in[2];
    const float* Wv = (const float*)d_in[3];
    const float* Wo = (const float*)d_in[4];
    const float* bo = (const float*)d_in[5];
    float* out = (float*)d_out;

    __half *Xh, *Wh, *Qh, *Kh, *Vh, *Ch;
    cudaGetSymbolAddress((void**)&Xh, g_Xh);
    cudaGetSymbolAddress((void**)&Wh, g_Wh);
    cudaGetSymbolAddress((void**)&Qh, g_Qh);
    cudaGetSymbolAddress((void**)&Kh, g_Kh);
    cudaGetSymbolAddress((void**)&Vh, g_Vh);
    cudaGetSymbolAddress((void**)&Ch, g_Ch);
    const float** wsrc;
    cudaGetSymbolAddress((void**)&wsrc, g_wsrc);

    cudaFuncSetAttribute(gemm_qkv, cudaFuncAttributeMaxDynamicSharedMemorySize, G_SMEM);
    cudaFuncSetAttribute(gemm_out, cudaFuncAttributeMaxDynamicSharedMemorySize, G_SMEM);
    cudaFuncSetAttribute(flash_h, cudaFuncAttributeMaxDynamicSharedMemorySize, F_SMEM);

    const int NX4 = BT * DM / 4;
    conv_x<<<NX4 / 256, 256>>>((const float4*)x, (__half2*)Xh, NX4);

    set_wsrc<<<1, 1>>>(Wq, Wk, Wv, Wo);
    dim3 tgrid(DM / 32, DM / 32, 4), tblk(32, 8);
    conv_wT<<<tgrid, tblk>>>(wsrc, Wh);

    dim3 qgrid(24, BT / 128);          // fused QKV
    gemm_qkv<<<qgrid, 128, G_SMEM>>>(Xh, Wh, Qh, Kh, Vh);

    dim3 fgrid(CTX / 128, NH, BATCH);  // (16, 16, 2)
    flash_h<<<fgrid, 128, F_SMEM>>>(Qh, Kh, Vh, Ch);

    dim3 ogrid(DM / 128, BT / 128);
    gemm_out<<<ogrid, 128, G_SMEM>>>(Ch, Wh + 3 * (size_t)DM * DM, bo, out);
}

// round 9
// speedup vs baseline: 2.5516x; 1.0135x over previous
#include <cuda_runtime.h>
#include <cuda_fp16.h>
#include <math.h>
#include <stdint.h>

#define BATCH 2
#define CTX   2048
#define DM    1024
#define NH    16
#define HD    64
#define BT    (BATCH*CTX)   // 4096

// ---------------- scratch (device globals; no allocation allowed) ----------
__device__ __half g_Xh[BT * DM];
__device__ __half g_Wh[4 * DM * DM];   // transposed weights [N][K], fp16
__device__ __half g_Qh[BT * DM];
__device__ __half g_Kh[BT * DM];
__device__ __half g_Vh[BT * DM];
__device__ __half g_Ch[BT * DM];

// Q projections pre-scaled by 1/sqrt(64) * log2(e): flash works in exp2 domain
#define QSCALE 0.18033688011112042f

// ---------------- helpers ---------------------------------------------------
__device__ __forceinline__ void mma_f16(float* d, const uint32_t* a, uint32_t b0, uint32_t b1) {
    asm volatile(
        "mma.sync.aligned.m16n8k16.row.col.f32.f16.f16.f32 "
        "{%0,%1,%2,%3}, {%4,%5,%6,%7}, {%8,%9}, {%0,%1,%2,%3};"
        : "+f"(d[0]), "+f"(d[1]), "+f"(d[2]), "+f"(d[3])
        : "r"(a[0]), "r"(a[1]), "r"(a[2]), "r"(a[3]), "r"(b0), "r"(b1));
}

__device__ __forceinline__ void ldm4(uint32_t* r, uint32_t addr) {
    asm volatile("ldmatrix.sync.aligned.m8n8.x4.shared.b16 {%0,%1,%2,%3}, [%4];"
                 : "=r"(r[0]), "=r"(r[1]), "=r"(r[2]), "=r"(r[3]) : "r"(addr));
}
__device__ __forceinline__ void ldm4t(uint32_t& r0, uint32_t& r1, uint32_t& r2, uint32_t& r3,
                                      uint32_t addr) {
    asm volatile("ldmatrix.sync.aligned.m8n8.x4.trans.shared.b16 {%0,%1,%2,%3}, [%4];"
                 : "=r"(r0), "=r"(r1), "=r"(r2), "=r"(r3) : "r"(addr));
}

__device__ __forceinline__ void cp16s(uint32_t dst, const void* g) {
    asm volatile("cp.async.ca.shared.global [%0], [%1], 16;" :: "r"(dst), "l"(g));
}
__device__ __forceinline__ void cp_commit() {
    asm volatile("cp.async.commit_group;" ::: "memory");
}
__device__ __forceinline__ uint32_t packh2(float x, float y) {
    __half2 h = __floats2half2_rn(x, y);
    return *(uint32_t*)&h;
}
__device__ __forceinline__ float ex2(float x) {
    float y; asm("ex2.approx.f32 %0, %1;" : "=f"(y) : "f"(x)); return y;
}

// ---------------- converters -------------------------------------------------
__global__ __launch_bounds__(256) void conv_x(const float4* __restrict__ in,
                                              __half2* __restrict__ out, int n4) {
    int i = blockIdx.x * 256 + threadIdx.x;
    if (i < n4) {
        float4 v = in[i];
        out[2 * i]     = __floats2half2_rn(v.x, v.y);
        out[2 * i + 1] = __floats2half2_rn(v.z, v.w);
    }
}

__device__ const float* g_wsrc[4];
// W[k][n] fp32 -> out[n][k] fp16  (4 matrices via blockIdx.z)
__global__ void conv_wT(const float* const* __restrict__ srcs, __half* __restrict__ out) {
    __shared__ float tle[32][33];
    const float* in = srcs[blockIdx.z];
    __half* o = out + (size_t)blockIdx.z * DM * DM;
    int bx = blockIdx.x * 32, by = blockIdx.y * 32;
    int tx = threadIdx.x, ty = threadIdx.y;
    #pragma unroll
    for (int i = 0; i < 4; i++)
        tle[ty + 8 * i][tx] = in[(size_t)(by + ty + 8 * i) * DM + bx + tx];
    __syncthreads();
    #pragma unroll
    for (int i = 0; i < 4; i++)
        o[(size_t)(bx + ty + 8 * i) * DM + by + tx] = __float2half_rn(tle[tx][ty + 8 * i]);
}

// ============================================================================
// fp16 GEMM core. BM=BN=128, BK=32, 4-stage cp.async, ONE sync per k-tile.
// 4 warps (2m x 2n), warp tile 64x64. Next-stage issue right after sync.
// ============================================================================
#define G_LD   40
#define G_STG  (128 * G_LD)
#define G_NSTG 4
#define G_SMEM (G_NSTG * 2 * G_STG * 2)    // 81920 B

struct GemmAcc { float a[4][8][4]; };

__device__ __forceinline__ void gemm_core(
    const __half* __restrict__ A, const __half* __restrict__ Bt,
    int row0, int col0, GemmAcc& acc, __half* gsm)
{
    const int tid = threadIdx.x;
    const int lane = tid & 31, wid = tid >> 5;
    const int wm = wid & 1, wn = wid >> 1;

    uint32_t sA = (uint32_t)__cvta_generic_to_shared(gsm);
    uint32_t sB = sA + G_NSTG * G_STG * 2;

    const int a_row = (lane & 7) + ((lane >> 3) & 1) * 8;
    const int a_kof = ((lane >> 4) & 1) * 8;
    const int b_row = (lane & 7) + ((lane >> 4) & 1) * 8;
    const int b_kof = ((lane >> 3) & 1) * 8;

    #pragma unroll
    for (int mt = 0; mt < 4; mt++)
        #pragma unroll
        for (int nt = 0; nt < 8; nt++)
            #pragma unroll
            for (int r = 0; r < 4; r++) acc.a[mt][nt][r] = 0.f;

    const int NT = DM / 32;   // 32
    auto issue = [&](int t) {
        if (t < NT) {
            int buf = t % G_NSTG, k0 = t * 32;
            #pragma unroll
            for (int i = 0; i < 4; i++) {
                int idx = tid + i * 128;
                int r = idx >> 2, c = idx & 3;
                uint32_t off = (uint32_t)(buf * G_STG + r * G_LD + c * 8) * 2;
                cp16s(sA + off, A  + (size_t)(row0 + r) * DM + k0 + c * 8);
                cp16s(sB + off, Bt + (size_t)(col0 + r) * DM + k0 + c * 8);
            }
        }
        cp_commit();
    };

    issue(0); issue(1); issue(2);

    for (int it = 0; it < NT; ++it) {
        asm volatile("cp.async.wait_group 2;" ::: "memory");
        __syncthreads();
        issue(it + 3);   // buffer (it-1)%4: consumed; all warps passed sync

        uint32_t ab = sA + (uint32_t)((it % G_NSTG) * G_STG) * 2;
        uint32_t bb = sB + (uint32_t)((it % G_NSTG) * G_STG) * 2;

        #pragma unroll
        for (int ks = 0; ks < 2; ks++) {
            uint32_t a[4][4];
            #pragma unroll
            for (int mt = 0; mt < 4; mt++)
                ldm4(a[mt], ab + (uint32_t)((wm * 64 + mt * 16 + a_row) * G_LD
                                            + ks * 16 + a_kof) * 2);
            #pragma unroll
            for (int ntp = 0; ntp < 4; ntp++) {
                uint32_t bf[4];
                ldm4(bf, bb + (uint32_t)((wn * 64 + ntp * 16 + b_row) * G_LD
                                         + ks * 16 + b_kof) * 2);
                #pragma unroll
                for (int mt = 0; mt < 4; mt++) {
                    mma_f16(acc.a[mt][2 * ntp],     a[mt], bf[0], bf[1]);
                    mma_f16(acc.a[mt][2 * ntp + 1], a[mt], bf[2], bf[3]);
                }
            }
        }
    }
}

// Fused QKV: grid (24, 32). mat = bx>>3 selects weight + destination.
__global__ __launch_bounds__(128, 2) void gemm_qkv(
    const __half* __restrict__ A, const __half* __restrict__ W,
    __half* __restrict__ Qh, __half* __restrict__ Kh, __half* __restrict__ Vh)
{
    extern __shared__ __align__(16) __half gsm[];
    const int mat = blockIdx.x >> 3;
    const int col0 = (blockIdx.x & 7) * 128;
    const int row0 = blockIdx.y * 128;
    const __half* Bt = W + (size_t)mat * DM * DM;
    __half* C = (mat == 0) ? Qh : (mat == 1) ? Kh : Vh;
    const float sc = (mat == 0) ? QSCALE : 1.f;

    GemmAcc acc;
    gemm_core(A, Bt, row0, col0, acc, gsm);

    const int lane = threadIdx.x & 31, wid = threadIdx.x >> 5;
    const int lr = lane >> 2, lc = lane & 3;
    const int wm = wid & 1, wn = wid >> 1;
    #pragma unroll
    for (int mt = 0; mt < 4; mt++) {
        int r = row0 + wm * 64 + mt * 16 + lr;
        #pragma unroll
        for (int nt = 0; nt < 8; nt++) {
            int c = col0 + wn * 64 + nt * 8 + 2 * lc;
            *(__half2*)&C[(size_t)r * DM + c] =
                __floats2half2_rn(acc.a[mt][nt][0] * sc, acc.a[mt][nt][1] * sc);
            *(__half2*)&C[(size_t)(r + 8) * DM + c] =
                __floats2half2_rn(acc.a[mt][nt][2] * sc, acc.a[mt][nt][3] * sc);
        }
    }
}

// Out projection: fp32 output + bias
__global__ __launch_bounds__(128, 2) void gemm_out(
    const __half* __restrict__ A, const __half* __restrict__ Bt,
    const float* __restrict__ bias, float* __restrict__ Cf)
{
    extern __shared__ __align__(16) __half gsm[];
    const int col0 = blockIdx.x * 128, row0 = blockIdx.y * 128;

    GemmAcc acc;
    gemm_core(A, Bt, row0, col0, acc, gsm);

    const int lane = threadIdx.x & 31, wid = threadIdx.x >> 5;
    const int lr = lane >> 2, lc = lane & 3;
    const int wm = wid & 1, wn = wid >> 1;
    #pragma unroll
    for (int mt = 0; mt < 4; mt++) {
        int r = row0 + wm * 64 + mt * 16 + lr;
        #pragma unroll
        for (int nt = 0; nt < 8; nt++) {
            int c = col0 + wn * 64 + nt * 8 + 2 * lc;
            float bx = bias[c], by = bias[c + 1];
            *(float2*)&Cf[(size_t)r * DM + c] =
                make_float2(acc.a[mt][nt][0] + bx, acc.a[mt][nt][1] + by);
            *(float2*)&Cf[(size_t)(r + 8) * DM + c] =
                make_float2(acc.a[mt][nt][2] + bx, acc.a[mt][nt][3] + by);
        }
    }
}

// ============================================================================
// fp16 flash attention (causal, exp2 domain). 128 q/CTA, 64 kv/tile.
// 4 warps x 32 q-rows. Q fragments hoisted into registers (loaded once).
// 3-buffer cp.async, ONE sync per tile, next tile issued right after S-mma.
// ============================================================================
#define F_LD   72
#define F_QP   (128 * F_LD)
#define F_KV   (64 * F_LD)
#define F_SMEM ((F_QP + 3 * F_KV + 3 * F_KV) * 2)   // 73728 B

__global__ __launch_bounds__(128, 2) void flash_h(
    const __half* __restrict__ Q, const __half* __restrict__ K,
    const __half* __restrict__ V, __half* __restrict__ O)
{
    extern __shared__ __align__(16) __half fsm[];
    const int tid = threadIdx.x;
    const int lane = tid & 31, wid = tid >> 5;
    const int lr = lane >> 2, lc = lane & 3;
    const int q0 = (gridDim.x - 1 - blockIdx.x) * 128;   // heavy tiles first
    const int h = blockIdx.y, b = blockIdx.z;

    const __half* Qg = Q + (size_t)(b * CTX) * DM + h * HD;
    const __half* Kg = K + (size_t)(b * CTX) * DM + h * HD;
    const __half* Vg = V + (size_t)(b * CTX) * DM + h * HD;

    uint32_t sQ = (uint32_t)__cvta_generic_to_shared(fsm);
    uint32_t sK = sQ + F_QP * 2;
    uint32_t sV = sK + 3 * F_KV * 2;

    const int a_row = (lane & 7) + ((lane >> 3) & 1) * 8;
    const int a_kof = ((lane >> 4) & 1) * 8;
    const int b_row = (lane & 7) + ((lane >> 4) & 1) * 8;
    const int b_kof = ((lane >> 3) & 1) * 8;

    const int nkv = q0 / 64 + 2;

    auto issueKV = [&](int t) {
        if (t < nkv) {
            int kb = t * 64, buf = t % 3;
            #pragma unroll
            for (int i = 0; i < 8; i++) {
                int idx = tid + i * 128;
                int sel = idx >> 9;
                int kk = (idx >> 3) & 63, c = idx & 7;
                const __half* src = (sel ? Vg : Kg) + (size_t)(kb + kk) * DM + c * 8;
                uint32_t dst = (sel ? sV : sK) +
                               (uint32_t)(buf * F_KV + kk * F_LD + c * 8) * 2;
                cp16s(dst, src);
            }
        }
        cp_commit();
    };

    // prologue: Q tile joins tile-0's commit group
    #pragma unroll
    for (int i = 0; i < 8; i++) {
        int idx = tid + i * 128;
        int q = idx >> 3, c = idx & 7;
        cp16s(sQ + (uint32_t)(q * F_LD + c * 8) * 2, Qg + (size_t)(q0 + q) * DM + c * 8);
    }
    issueKV(0);
    issueKV(1);

    const int qw = wid * 32;
    const int vrow = lane & 15;
    const int vblk = lane >> 4;

    // ---- hoist Q fragments: loaded once, reused for every kv tile ----
    asm volatile("cp.async.wait_group 1;" ::: "memory");   // group 0 (Q + KV0) done
    __syncthreads();
    uint32_t qa[4][2][4];
    #pragma unroll
    for (int ks = 0; ks < 4; ks++)
        #pragma unroll
        for (int mt = 0; mt < 2; mt++)
            ldm4(qa[ks][mt], sQ + (uint32_t)((qw + mt * 16 + a_row) * F_LD
                                             + ks * 16 + a_kof) * 2);

    float m0[2], m1[2], l0[2], l1[2];
    float o[2][8][4];
    #pragma unroll
    for (int mt = 0; mt < 2; mt++) {
        m0[mt] = -INFINITY; m1[mt] = -INFINITY; l0[mt] = 0.f; l1[mt] = 0.f;
        #pragma unroll
        for (int dt = 0; dt < 8; dt++)
            #pragma unroll
            for (int r = 0; r < 4; r++) o[mt][dt][r] = 0.f;
    }

    for (int t = 0; t < nkv; ++t) {
        asm volatile("cp.async.wait_group 1;" ::: "memory");
        __syncthreads();

        uint32_t kbuf = sK + (uint32_t)((t % 3) * F_KV) * 2;
        uint32_t vbuf = sV + (uint32_t)((t % 3) * F_KV) * 2;

        // ---- S = Q @ K^T (warp: 32 x 64), log2 domain ----
        float s[2][8][4];
        #pragma unroll
        for (int mt = 0; mt < 2; mt++)
            #pragma unroll
            for (int nt = 0; nt < 8; nt++)
                #pragma unroll
                for (int r = 0; r < 4; r++) s[mt][nt][r] = 0.f;

        #pragma unroll
        for (int ks = 0; ks < 4; ks++) {
            #pragma unroll
            for (int ntp = 0; ntp < 4; ntp++) {
                uint32_t bf[4];
                ldm4(bf, kbuf + (uint32_t)((ntp * 16 + b_row) * F_LD
                                           + ks * 16 + b_kof) * 2);
                #pragma unroll
                for (int mt = 0; mt < 2; mt++) {
                    mma_f16(s[mt][2 * ntp],     qa[ks][mt], bf[0], bf[1]);
                    mma_f16(s[mt][2 * ntp + 1], qa[ks][mt], bf[2], bf[3]);
                }
            }
        }

        // issue next-next tile now: its buffer was consumed in iter t-1,
        // and the top-of-loop sync proves all warps are past it.
        issueKV(t + 2);

        const int kb = t * 64;

        if (kb + 63 > q0) {
            #pragma unroll
            for (int mt = 0; mt < 2; mt++) {
                int r0 = q0 + qw + mt * 16 + lr, r1 = r0 + 8;
                #pragma unroll
                for (int nt = 0; nt < 8; nt++) {
                    #pragma unroll
                    for (int j = 0; j < 2; j++) {
                        int key = kb + nt * 8 + 2 * lc + j;
                        if (key > r0) s[mt][nt][j]     = -1e30f;
                        if (key > r1) s[mt][nt][2 + j] = -1e30f;
                    }
                }
            }
        }

        // ---- online softmax (exp2 domain) ----
        #pragma unroll
        for (int mt = 0; mt < 2; mt++) {
            float rm0 = -1e30f, rm1 = -1e30f;
            #pragma unroll
            for (int nt = 0; nt < 8; nt++) {
                rm0 = fmaxf(rm0, fmaxf(s[mt][nt][0], s[mt][nt][1]));
                rm1 = fmaxf(rm1, fmaxf(s[mt][nt][2], s[mt][nt][3]));
            }
            rm0 = fmaxf(rm0, __shfl_xor_sync(0xffffffffu, rm0, 1));
            rm0 = fmaxf(rm0, __shfl_xor_sync(0xffffffffu, rm0, 2));
            rm1 = fmaxf(rm1, __shfl_xor_sync(0xffffffffu, rm1, 1));
            rm1 = fmaxf(rm1, __shfl_xor_sync(0xffffffffu, rm1, 2));

            float mn0 = fmaxf(m0[mt], rm0), mn1 = fmaxf(m1[mt], rm1);
            float c0 = ex2(m0[mt] - mn0), c1 = ex2(m1[mt] - mn1);
            float rs0 = 0.f, rs1 = 0.f;
            #pragma unroll
            for (int nt = 0; nt < 8; nt++) {
                s[mt][nt][0] = ex2(s[mt][nt][0] - mn0);
                s[mt][nt][1] = ex2(s[mt][nt][1] - mn0);
                s[mt][nt][2] = ex2(s[mt][nt][2] - mn1);
                s[mt][nt][3] = ex2(s[mt][nt][3] - mn1);
                rs0 += s[mt][nt][0] + s[mt][nt][1];
                rs1 += s[mt][nt][2] + s[mt][nt][3];
            }
            rs0 += __shfl_xor_sync(0xffffffffu, rs0, 1);
            rs0 += __shfl_xor_sync(0xffffffffu, rs0, 2);
            rs1 += __shfl_xor_sync(0xffffffffu, rs1, 1);
            rs1 += __shfl_xor_sync(0xffffffffu, rs1, 2);

            l0[mt] = l0[mt] * c0 + rs0; m0[mt] = mn0;
            l1[mt] = l1[mt] * c1 + rs1; m1[mt] = mn1;
            #pragma unroll
            for (int dt = 0; dt < 8; dt++) {
                o[mt][dt][0] *= c0; o[mt][dt][1] *= c0;
                o[mt][dt][2] *= c1; o[mt][dt][3] *= c1;
            }
        }

        // ---- O += P @ V : P packed from registers ----
        #pragma unroll
        for (int ks = 0; ks < 4; ks++) {
            uint32_t a[2][4];
            #pragma unroll
            for (int mt = 0; mt < 2; mt++) {
                a[mt][0] = packh2(s[mt][2 * ks][0],     s[mt][2 * ks][1]);
                a[mt][1] = packh2(s[mt][2 * ks][2],     s[mt][2 * ks][3]);
                a[mt][2] = packh2(s[mt][2 * ks + 1][0], s[mt][2 * ks + 1][1]);
                a[mt][3] = packh2(s[mt][2 * ks + 1][2], s[mt][2 * ks + 1][3]);
            }
            #pragma unroll
            for (int ntp = 0; ntp < 4; ntp++) {
                uint32_t b0, b1, b2, b3;
                uint32_t addr = vbuf +
                    (uint32_t)((ks * 16 + vrow) * F_LD + (2 * ntp + vblk) * 8) * 2;
                ldm4t(b0, b1, b2, b3, addr);
                #pragma unroll
                for (int mt = 0; mt < 2; mt++) {
                    mma_f16(o[mt][2 * ntp],     a[mt], b0, b1);
                    mma_f16(o[mt][2 * ntp + 1], a[mt], b2, b3);
                }
            }
        }
    }

    // ---- normalize + write ctx (fp16) ----
    __half* Og = O + (size_t)(b * CTX) * DM + h * HD;
    #pragma unroll
    for (int mt = 0; mt < 2; mt++) {
        float i0 = 1.f / l0[mt], i1 = 1.f / l1[mt];
        int r0 = q0 + qw + mt * 16 + lr;
        #pragma unroll
        for (int dt = 0; dt < 8; dt++) {
            int c = dt * 8 + 2 * lc;
            *(__half2*)&Og[(size_t)r0 * DM + c] =
                __floats2half2_rn(o[mt][dt][0] * i0, o[mt][dt][1] * i0);
            *(__half2*)&Og[(size_t)(r0 + 8) * DM + c] =
                __floats2half2_rn(o[mt][dt][2] * i1, o[mt][dt][3] * i1);
        }
    }
}

// ---- tiny kernel to publish weight source pointers (graph-capturable) ----
__global__ void set_wsrc(const float* wq, const float* wk, const float* wv, const float* wo) {
    g_wsrc[0] = wq; g_wsrc[1] = wk; g_wsrc[2] = wv; g_wsrc[3] = wo;
}

// ============================================================================
// launch
// ============================================================================
extern "C" void kernel_launch(void* const* d_in, const int* in_sizes, int n_in,
                              void* d_out, int out_size)
{
    const float* x  = (const float*)d_in[0];
    const float* Wq = (const float*)d_in[1];
    const float* Wk = (const float*)d_in[2];
    const float* Wv = (const float*)d_in[3];
    const float* Wo = (const float*)d_in[4];
    const float* bo = (const float*)d_in[5];
    float* out = (float*)d_out;

    __half *Xh, *Wh, *Qh, *Kh, *Vh, *Ch;
    cudaGetSymbolAddress((void**)&Xh, g_Xh);
    cudaGetSymbolAddress((void**)&Wh, g_Wh);
    cudaGetSymbolAddress((void**)&Qh, g_Qh);
    cudaGetSymbolAddress((void**)&Kh, g_Kh);
    cudaGetSymbolAddress((void**)&Vh, g_Vh);
    cudaGetSymbolAddress((void**)&Ch, g_Ch);
    const float** wsrc;
    cudaGetSymbolAddress((void**)&wsrc, g_wsrc);

    cudaFuncSetAttribute(gemm_qkv, cudaFuncAttributeMaxDynamicSharedMemorySize, G_SMEM);
    cudaFuncSetAttribute(gemm_out, cudaFuncAttributeMaxDynamicSharedMemorySize, G_SMEM);
    cudaFuncSetAttribute(flash_h, cudaFuncAttributeMaxDynamicSharedMemorySize, F_SMEM);

    const int NX4 = BT * DM / 4;
    conv_x<<<NX4 / 256, 256>>>((const float4*)x, (__half2*)Xh, NX4);

    set_wsrc<<<1, 1>>>(Wq, Wk, Wv, Wo);
    dim3 tgrid(DM / 32, DM / 32, 4), tblk(32, 8);
    conv_wT<<<tgrid, tblk>>>(wsrc, Wh);

    dim3 qgrid(24, BT / 128);          // fused QKV
    gemm_qkv<<<qgrid, 128, G_SMEM>>>(Xh, Wh, Qh, Kh, Vh);

    dim3 fgrid(CTX / 128, NH, BATCH);  // (16, 16, 2)
    flash_h<<<fgrid, 128, F_SMEM>>>(Qh, Kh, Vh, Ch);

    dim3 ogrid(DM / 128, BT / 128);
    gemm_out<<<ogrid, 128, G_SMEM>>>(Ch, Wh + 3 * (size_t)DM * DM, bo, out);
}